// round 12
// baseline (speedup 1.0000x reference)
#include <cuda_runtime.h>
#include <cuda_fp16.h>
#include <math.h>
#include <stdint.h>

#define D_DIM 1024
#define H_DIM 2048
#define E_NUM 8
#define CAP   8192
#define N_TOK 8192
#define BM 128
#define BN 256
#define BK 64                            // halves per slab = 128 B rows

#define A_BYTES 16384                    // 128 rows x 128B
#define B_BYTES 32768                    // 256 rows x 128B
#define STAGE_BYTES (A_BYTES + B_BYTES)  // 49152
#define NSTAGE 4
#define SMEM_TOTAL (1024 + NSTAGE * STAGE_BYTES)  // 197632

// ---------------- device scratch ----------------
__device__ int    g_cnt[E_NUM];
__device__ int    g_off[E_NUM];
__device__ int    g_tok[E_NUM * CAP];
__device__ float  g_gate[E_NUM * CAP];
__device__ int    g_inv[N_TOK * 2];
__device__ float  g_imp[E_NUM];
__device__ float  g_ent;
__device__ __half g_xh[(size_t)N_TOK * D_DIM];            // x as half, k-permuted
__device__ __half g_hh[(size_t)N_TOK * 2 * H_DIM];        // h as half, k-permuted
__device__ __half g_yh[(size_t)N_TOK * 2 * D_DIM];        // gate*y as half
__device__ __half g_w1h[(size_t)E_NUM * H_DIM * D_DIM];   // [e][n=H][k'=D]
__device__ __half g_w2h[(size_t)E_NUM * D_DIM * H_DIM];   // [e][n=D][k'=H]

// k-group permutation: storage slot s holds source k = KORD[s]
__device__ __constant__ int KORD[16] = {0,1,8,9,2,3,10,11,4,5,12,13,6,7,14,15};
__device__ __forceinline__ int kslot(int r) {      // r = k & 15, even
    return (((r >> 1) & 3) << 2) + ((r >> 3) << 1);
}

// ---------------- helpers ----------------
__device__ __forceinline__ uint32_t smem_u32(const void* p) {
    uint32_t a;
    asm("{ .reg .u64 t; cvta.to.shared.u64 t, %1; cvt.u32.u64 %0, t; }" : "=r"(a) : "l"(p));
    return a;
}
#define CP16(dst, src) \
    asm volatile("cp.async.cg.shared.global [%0], [%1], 16;" :: "r"(dst), "l"(src))
#define CP_COMMIT()  asm volatile("cp.async.commit_group;" ::: "memory")
#define CP_WAIT(n)   asm volatile("cp.async.wait_group %0;" :: "n"(n) : "memory")

__device__ __forceinline__ void mma_f16(float* c, unsigned a0, unsigned a1,
                                        unsigned a2, unsigned a3,
                                        unsigned b0, unsigned b1) {
    asm volatile(
        "mma.sync.aligned.m16n8k16.row.col.f32.f16.f16.f32 "
        "{%0,%1,%2,%3}, {%4,%5,%6,%7}, {%8,%9}, {%0,%1,%2,%3};\n"
        : "+f"(c[0]), "+f"(c[1]), "+f"(c[2]), "+f"(c[3])
        : "r"(a0), "r"(a1), "r"(a2), "r"(a3), "r"(b0), "r"(b1));
}
__device__ __forceinline__ float gelu_exact(float v) {
    return 0.5f * v * (1.0f + erff(v * 0.70710678118654752440f));
}

// ---------------- shared bodies ----------------
// W[e][k][n] fp32 -> WT[e][n][k'] half, one 64x64 tile.
__device__ __forceinline__ void wtrans_body(const float* __restrict__ W,
                                            __half* __restrict__ WT,
                                            int K, int N, int nbi, int kbi, int e,
                                            float (*t)[68]) {
    int n0 = nbi * 64, k0 = kbi * 64;
    const float* Ws = W + (size_t)e * K * N + (size_t)k0 * N + n0;
    __half* Wd = WT + (size_t)e * N * K;
#pragma unroll
    for (int i = 0; i < 4; i++) {
        int idx = threadIdx.x + 256 * i;     // 0..1023
        int kr = idx >> 4, c4 = idx & 15;
        float4 v = *reinterpret_cast<const float4*>(Ws + (size_t)kr * N + c4 * 4);
        int cs = (c4 * 4) ^ (((kr >> 4) & 3) << 3);   // 8-multiple XOR: float4-safe
        *reinterpret_cast<float4*>(&t[kr][cs]) = v;
    }
    __syncthreads();
    int n = threadIdx.x >> 2, kg = (threadIdx.x & 3) * 16;
    __half hh[16];
#pragma unroll
    for (int s = 0; s < 16; s++) {
        int row = kg + KORD[s];
        hh[s] = __float2half(t[row][n ^ (((row >> 4) & 3) << 3)]);
    }
    __half* drow = Wd + (size_t)(n0 + n) * K + k0 + kg;
    *reinterpret_cast<uint4*>(drow)     = *reinterpret_cast<uint4*>(hh);
    *reinterpret_cast<uint4*>(drow + 8) = *reinterpret_cast<uint4*>(hh + 8);
}

// ---------------- small kernels ----------------
__global__ void reset_k() {
    int t = threadIdx.x;
    if (t < E_NUM) { g_cnt[t] = 0; g_imp[t] = 0.0f; }
    if (t == 0)    g_ent = 0.0f;
}

// prelude: blocks [0,1024) = router (+x->half), blocks [1024,5120) = W1 transpose
__global__ void prelude_k(const float* __restrict__ x,
                          const float* __restrict__ gW,
                          const float* __restrict__ gb,
                          const float* __restrict__ W1) {
    __shared__ __align__(16) char smbuf[32768];

    if (blockIdx.x >= 1024) {
        int lin = blockIdx.x - 1024;         // W1: N=H_DIM (32 tiles), K=D_DIM (16 tiles)
        wtrans_body(W1, g_w1h, D_DIM, H_DIM,
                    lin & 31, (lin >> 5) & 15, lin >> 9,
                    reinterpret_cast<float(*)[68]>(smbuf));
        return;
    }

    float4* sgW = reinterpret_cast<float4*>(smbuf);   // 32 KB, 16B-swizzled
    int tid = threadIdx.x;
    for (int s = tid; s < 2048; s += 256)
        sgW[s ^ ((s >> 3) & 7)] = reinterpret_cast<const float4*>(gW)[s];
    __syncthreads();

    int token = (blockIdx.x * blockDim.x + tid) >> 5;
    int lane  = tid & 31;
    const float* xr = x + (size_t)token * D_DIM;
    __half* xh = g_xh + (size_t)token * D_DIM;

    float acc[8] = {0.f,0.f,0.f,0.f,0.f,0.f,0.f,0.f};
#pragma unroll
    for (int i = 0; i < 8; i++) {
        int d = lane * 4 + 128 * i;
        float4 xv = *reinterpret_cast<const float4*>(xr + d);
        int base = d & ~15, r = d & 15;
        *reinterpret_cast<__half2*>(xh + base + kslot(r)) =
            __floats2half2_rn(xv.x, xv.y);
        *reinterpret_cast<__half2*>(xh + base + kslot(r + 2)) =
            __floats2half2_rn(xv.z, xv.w);
        float xs[4] = {xv.x, xv.y, xv.z, xv.w};
#pragma unroll
        for (int q = 0; q < 4; q++) {
            int s0 = (d + q) * 2;
            float4 wa = sgW[s0 ^ ((s0 >> 3) & 7)];
            int s1 = s0 + 1;
            float4 wb = sgW[s1 ^ ((s1 >> 3) & 7)];
            acc[0] += xs[q] * wa.x; acc[1] += xs[q] * wa.y;
            acc[2] += xs[q] * wa.z; acc[3] += xs[q] * wa.w;
            acc[4] += xs[q] * wb.x; acc[5] += xs[q] * wb.y;
            acc[6] += xs[q] * wb.z; acc[7] += xs[q] * wb.w;
        }
    }
#pragma unroll
    for (int e = 0; e < 8; e++)
#pragma unroll
        for (int o = 16; o; o >>= 1) acc[e] += __shfl_xor_sync(0xffffffffu, acc[e], o);
    if (lane) return;

    float lg[8];
#pragma unroll
    for (int e = 0; e < 8; e++) lg[e] = acc[e] + gb[e];
    float mx = lg[0];
#pragma unroll
    for (int e = 1; e < 8; e++) mx = fmaxf(mx, lg[e]);
    float p[8], Z = 0.f;
#pragma unroll
    for (int e = 0; e < 8; e++) { p[e] = expf(lg[e] - mx); Z += p[e]; }
    float ent = 0.f;
#pragma unroll
    for (int e = 0; e < 8; e++) {
        p[e] /= Z;
        ent -= p[e] * logf(p[e] + 1e-8f);
        atomicAdd(&g_imp[e], p[e]);
    }
    atomicAdd(&g_ent, ent);

    int e0 = 0;
#pragma unroll
    for (int e = 1; e < 8; e++) if (lg[e] > lg[e0]) e0 = e;
    int e1 = -1;
#pragma unroll
    for (int e = 0; e < 8; e++) if (e != e0 && (e1 < 0 || lg[e] > lg[e1])) e1 = e;

    float dlt = expf(lg[e1] - lg[e0]);
    float g0 = 1.0f / (1.0f + dlt);
    float g1 = dlt / (1.0f + dlt);

    int s0 = atomicAdd(&g_cnt[e0], 1);
    g_tok[e0 * CAP + s0] = token; g_gate[e0 * CAP + s0] = g0;
    int s1 = atomicAdd(&g_cnt[e1], 1);
    g_tok[e1 * CAP + s1] = token; g_gate[e1 * CAP + s1] = g1;
    g_inv[token * 2 + 0] = e0 * CAP + s0;
    g_inv[token * 2 + 1] = e1 * CAP + s1;
}

__global__ void tail_k(float* __restrict__ out_tail) {
    if (threadIdx.x != 0 || blockIdx.x != 0) return;
    int off = 0;
    float loadv[8], impv[8];
    for (int e = 0; e < 8; e++) { g_off[e] = off; off += g_cnt[e]; }
    for (int e = 0; e < 8; e++) {
        loadv[e] = (float)g_cnt[e] / (float)N_TOK;
        impv[e]  = g_imp[e] / (float)N_TOK;
    }
    float bal = 0.f, util = 0.f;
    for (int e = 0; e < 8; e++) bal += impv[e] * loadv[e];
    bal *= (float)E_NUM;
    for (int e = 0; e < 8; e++) util -= loadv[e] * logf(loadv[e] + 1e-8f);
    out_tail[0] = bal;
    out_tail[1] = g_ent / (float)N_TOK;
    out_tail[2] = util;
    for (int e = 0; e < 8; e++) out_tail[3 + e]  = loadv[e];
    for (int e = 0; e < 8; e++) out_tail[11 + e] = impv[e];
}

// ---------------- persistent fp16 grouped GEMM (128x256, warp 64x64, BK=64) ----------------
// MODE 0: tiles [0,4096) GEMM1 (g_xh @ g_w1h -> gelu -> g_hh), [4096,8192) W2 transpose
// MODE 1: tiles [0,2048) GEMM2 (g_hh @ g_w2h -> gate*(c+bias) -> g_yh)
template <int MODE>
__device__ __forceinline__ void gemm_ptrs(int m_base, int n_base, int e, int cnt,
                                          int cch, int r0,
                                          const __half** aSrc, const __half*& bSrc) {
    constexpr int Kdim  = (MODE == 0) ? D_DIM : H_DIM;
    constexpr int Ncols = (MODE == 0) ? H_DIM : D_DIM;
    const __half* Ab = (MODE == 0) ? (const __half*)g_xh : (const __half*)g_hh;
    const __half* Wb = (MODE == 0) ? (const __half*)g_w1h : (const __half*)g_w2h;
    const int hoff = g_off[e];
#pragma unroll
    for (int i = 0; i < 4; i++) {
        int am = m_base + r0 + 32 * i;
        if (am >= cnt) am = cnt - 1;
        size_t row = (MODE == 0) ? (size_t)g_tok[e * CAP + am] : (size_t)(hoff + am);
        aSrc[i] = Ab + row * Kdim + cch * 8;
    }
    bSrc = Wb + ((size_t)e * Ncols + n_base + r0) * Kdim + cch * 8;
}

template <int MODE>
__device__ __forceinline__ void issue_stage(int s, uint32_t aDst, uint32_t bDst,
                                            const __half* const* aSrc,
                                            const __half* bSrc) {
    constexpr int Kdim = (MODE == 0) ? D_DIM : H_DIM;
    constexpr int NS   = Kdim / BK;
    if (s < NS) {
        const int kb = s * BK;
        const uint32_t so = (uint32_t)((s & (NSTAGE - 1)) * STAGE_BYTES);
#pragma unroll
        for (int i = 0; i < 4; i++)
            CP16(aDst + so + i * 4096, aSrc[i] + kb);
#pragma unroll
        for (int i = 0; i < 8; i++)
            CP16(bDst + so + i * 4096, bSrc + (size_t)(32 * i) * Kdim + kb);
    }
    CP_COMMIT();
}

template <int MODE>
__global__ void __launch_bounds__(256, 1)
gemm_h(const float* __restrict__ bias, const float* __restrict__ W2) {
    constexpr int Kdim  = (MODE == 0) ? D_DIM : H_DIM;
    constexpr int Ncols = (MODE == 0) ? H_DIM : D_DIM;
    constexpr int NS    = Kdim / BK;
    constexpr int NTG   = (MODE == 0) ? 4096 : 2048;   // GEMM tiles
    constexpr int NTT   = (MODE == 0) ? 8192 : 2048;   // + transpose tiles

    extern __shared__ char smem[];
    const int tid = threadIdx.x, wid = tid >> 5, lane = tid & 31;
    const int g = lane >> 2, tig = lane & 3;
    const int wm = (wid & 1) * 64;
    const int wn = (wid >> 1) * 64;
    const int cch = tid & 7;
    const int r0  = tid >> 3;
    const uint32_t sb   = smem_u32(smem);
    const uint32_t swz  = (uint32_t)((cch ^ (r0 & 7)) << 4);
    const uint32_t aDst = sb + 1024 + r0 * 128 + swz;
    const uint32_t bDst = sb + 1024 + A_BYTES + r0 * 128 + swz;
    const int aRow = (wm + g) * 128;
    const int bRow = A_BYTES + (wn + g) * 128;

    bool pref = false;

    for (int t = blockIdx.x; t < NTT; t += gridDim.x) {
        if (MODE == 0 && t >= NTG) {
            __syncthreads();                 // prior tile's smem reads done
            int lin = t - NTG;               // W2: N=D_DIM (16 tiles), K=H_DIM (32)
            wtrans_body(W2, g_w2h, H_DIM, D_DIM,
                        lin & 15, (lin >> 4) & 31, lin >> 9,
                        reinterpret_cast<float(*)[68]>(smem));
            __syncthreads();
            continue;
        }
        int bx, by, e;
        if (MODE == 0) { bx = t & 7; by = (t >> 3) & 63; e = t >> 9; }
        else           { bx = t & 3; by = (t >> 2) & 63; e = t >> 8; }
        const int cnt = g_cnt[e];
        const int m_base = by * BM;
        if (m_base >= cnt) continue;         // pref is false here by construction
        const int n_base = bx * BN;
        const int hoff = g_off[e];

        const __half* aSrc[4];
        const __half* bSrc;
        gemm_ptrs<MODE>(m_base, n_base, e, cnt, cch, r0, aSrc, bSrc);

        if (!pref) {
            issue_stage<MODE>(0, aDst, bDst, aSrc, bSrc);
            issue_stage<MODE>(1, aDst, bDst, aSrc, bSrc);
            issue_stage<MODE>(2, aDst, bDst, aSrc, bSrc);
        }
        pref = false;

        float c[4][8][4];
#pragma unroll
        for (int i = 0; i < 4; i++)
#pragma unroll
            for (int j = 0; j < 8; j++)
#pragma unroll
                for (int r = 0; r < 4; r++) c[i][j][r] = 0.f;

        for (int s = 0; s < NS; s++) {
            CP_WAIT(2);
            __syncthreads();
            issue_stage<MODE>(s + 3, aDst, bDst, aSrc, bSrc);

            const char* stg = smem + 1024 + (s & (NSTAGE - 1)) * STAGE_BYTES;
#pragma unroll
            for (int kx = 0; kx < 4; kx++) {
                const int off = (((2 * kx + (tig >> 1)) ^ g) << 4) + 8 * (tig & 1);
                uint2 ua0[4], ua1[4], ub[8];
#pragma unroll
                for (int i = 0; i < 4; i++) {
                    ua0[i] = *(const uint2*)(stg + aRow + i * 2048 + off);
                    ua1[i] = *(const uint2*)(stg + aRow + i * 2048 + 1024 + off);
                }
#pragma unroll
                for (int j = 0; j < 8; j++)
                    ub[j] = *(const uint2*)(stg + bRow + j * 1024 + off);
#pragma unroll
                for (int i = 0; i < 4; i++)
#pragma unroll
                    for (int j = 0; j < 8; j++)
                        mma_f16(c[i][j], ua0[i].x, ua1[i].x, ua0[i].y, ua1[i].y,
                                ub[j].x, ub[j].y);
            }
        }
        __syncthreads();                     // all stage reads done

        // bias for this tile (regs; smem stages may be prefetch-reused)
        float2 bv[8];
#pragma unroll
        for (int j = 0; j < 8; j++)
            bv[j] = *reinterpret_cast<const float2*>(
                bias + (size_t)e * Ncols + n_base + wn + j * 8 + tig * 2);

        // cross-tile prefetch: next tile's stages 0-2 issued under the epilogue
        {
            int nt = t + gridDim.x;
            if (nt < NTG) {
                int nbx, nby, ne;
                if (MODE == 0) { nbx = nt & 7; nby = (nt >> 3) & 63; ne = nt >> 9; }
                else           { nbx = nt & 3; nby = (nt >> 2) & 63; ne = nt >> 8; }
                int ncnt = g_cnt[ne];
                if (nby * BM < ncnt) {
                    const __half* naSrc[4];
                    const __half* nbSrc;
                    gemm_ptrs<MODE>(nby * BM, nbx * BN, ne, ncnt, cch, r0, naSrc, nbSrc);
                    issue_stage<MODE>(0, aDst, bDst, naSrc, nbSrc);
                    issue_stage<MODE>(1, aDst, bDst, naSrc, nbSrc);
                    issue_stage<MODE>(2, aDst, bDst, naSrc, nbSrc);
                    pref = true;
                }
            }
        }

        // ---- epilogue ----
#pragma unroll
        for (int i = 0; i < 4; i++) {
#pragma unroll
            for (int half = 0; half < 2; half++) {
                int mrow = m_base + wm + 16 * i + g + half * 8;
                if (mrow >= cnt) continue;
                if (MODE == 0) {
                    __half* hp = g_hh + (size_t)(hoff + mrow) * H_DIM + n_base;
#pragma unroll
                    for (int j = 0; j < 8; j++) {
                        int col = wn + j * 8 + tig * 2;
                        float v0 = c[i][j][half * 2 + 0] + bv[j].x;
                        float v1 = c[i][j][half * 2 + 1] + bv[j].y;
                        int col2 = (col & ~15) + kslot(col & 15);   // permuted store
                        *reinterpret_cast<__half2*>(hp + col2) =
                            __floats2half2_rn(gelu_exact(v0), gelu_exact(v1));
                    }
                } else {
                    float gate = g_gate[e * CAP + mrow];
                    __half* yp = g_yh + (size_t)(hoff + mrow) * D_DIM + n_base;
#pragma unroll
                    for (int j = 0; j < 8; j++) {
                        int col = wn + j * 8 + tig * 2;
                        float v0 = gate * (c[i][j][half * 2 + 0] + bv[j].x);
                        float v1 = gate * (c[i][j][half * 2 + 1] + bv[j].y);
                        *reinterpret_cast<__half2*>(yp + col) = __floats2half2_rn(v0, v1);
                    }
                }
            }
        }
    }
}

// ---------------- LayerNorm (y pre-gated, fp16) ----------------
__global__ void ln_k(const float* __restrict__ x,
                     const float* __restrict__ gamma,
                     const float* __restrict__ beta,
                     float* __restrict__ out) {
    int t = blockIdx.x;
    int tid = threadIdx.x;
    int lane = tid & 31, wid = tid >> 5;

    int i0 = g_inv[t * 2 + 0], i1 = g_inv[t * 2 + 1];
    size_t r0 = (size_t)(g_off[i0 >> 13] + (i0 & (CAP - 1)));
    size_t r1 = (size_t)(g_off[i1 >> 13] + (i1 & (CAP - 1)));
    const __half* y0 = g_yh + r0 * D_DIM;
    const __half* y1 = g_yh + r1 * D_DIM;
    const float* xr = x + (size_t)t * D_DIM;

    int c = tid * 4;
    float4 xv = *reinterpret_cast<const float4*>(xr + c);
    __half2 a01 = *reinterpret_cast<const __half2*>(y0 + c);
    __half2 a23 = *reinterpret_cast<const __half2*>(y0 + c + 2);
    __half2 b01 = *reinterpret_cast<const __half2*>(y1 + c);
    __half2 b23 = *reinterpret_cast<const __half2*>(y1 + c + 2);
    float2 fa01 = __half22float2(a01), fa23 = __half22float2(a23);
    float2 fb01 = __half22float2(b01), fb23 = __half22float2(b23);
    float z0 = xv.x + fa01.x + fb01.x;
    float z1 = xv.y + fa01.y + fb01.y;
    float z2 = xv.z + fa23.x + fb23.x;
    float z3 = xv.w + fa23.y + fb23.y;

    float s  = z0 + z1 + z2 + z3;
    float sq = z0 * z0 + z1 * z1 + z2 * z2 + z3 * z3;
#pragma unroll
    for (int o = 16; o; o >>= 1) {
        s  += __shfl_xor_sync(0xffffffffu, s, o);
        sq += __shfl_xor_sync(0xffffffffu, sq, o);
    }
    __shared__ float ws[8], wq[8];
    if (lane == 0) { ws[wid] = s; wq[wid] = sq; }
    __syncthreads();
    if (wid == 0) {
        float s2 = (lane < 8) ? ws[lane] : 0.f;
        float q2 = (lane < 8) ? wq[lane] : 0.f;
#pragma unroll
        for (int o = 4; o; o >>= 1) {
            s2 += __shfl_xor_sync(0xffffffffu, s2, o);
            q2 += __shfl_xor_sync(0xffffffffu, q2, o);
        }
        if (lane == 0) { ws[0] = s2; wq[0] = q2; }
    }
    __syncthreads();
    float mu  = ws[0] * (1.0f / D_DIM);
    float var = wq[0] * (1.0f / D_DIM) - mu * mu;
    float inv = rsqrtf(var + 1e-5f);

    float4 gm = *reinterpret_cast<const float4*>(gamma + c);
    float4 bt = *reinterpret_cast<const float4*>(beta + c);
    float4 o;
    o.x = (z0 - mu) * inv * gm.x + bt.x;
    o.y = (z1 - mu) * inv * gm.y + bt.y;
    o.z = (z2 - mu) * inv * gm.z + bt.z;
    o.w = (z3 - mu) * inv * gm.w + bt.w;
    *reinterpret_cast<float4*>(out + (size_t)t * D_DIM + c) = o;
}

// ---------------- launch ----------------
extern "C" void kernel_launch(void* const* d_in, const int* in_sizes, int n_in,
                              void* d_out, int out_size) {
    (void)in_sizes; (void)n_in; (void)out_size;
    const float* x     = (const float*)d_in[0];
    const float* gW    = (const float*)d_in[1];
    const float* gb    = (const float*)d_in[2];
    const float* W1    = (const float*)d_in[3];
    const float* b1    = (const float*)d_in[4];
    const float* W2    = (const float*)d_in[5];
    const float* b2    = (const float*)d_in[6];
    const float* gamma = (const float*)d_in[7];
    const float* beta  = (const float*)d_in[8];
    float* out = (float*)d_out;

    static int nsm = 0;
    if (nsm == 0) {
        cudaDeviceGetAttribute(&nsm, cudaDevAttrMultiProcessorCount, 0);
        if (nsm <= 0) nsm = 148;
        cudaFuncSetAttribute((const void*)gemm_h<0>,
                             cudaFuncAttributeMaxDynamicSharedMemorySize, SMEM_TOTAL);
        cudaFuncSetAttribute((const void*)gemm_h<1>,
                             cudaFuncAttributeMaxDynamicSharedMemorySize, SMEM_TOTAL);
    }

    reset_k<<<1, 32>>>();
    prelude_k<<<1024 + 4096, 256>>>(x, gW, gb, W1);      // router + W1 transpose
    tail_k<<<1, 1>>>(out + (size_t)N_TOK * D_DIM);
    gemm_h<0><<<nsm, 256, SMEM_TOTAL>>>(b1, W2);          // GEMM1 + W2 transpose
    gemm_h<1><<<nsm, 256, SMEM_TOTAL>>>(b2, nullptr);     // GEMM2
    ln_k<<<N_TOK, 256>>>(x, gamma, beta, out);
}

// round 13
// speedup vs baseline: 1.1183x; 1.1183x over previous
#include <cuda_runtime.h>
#include <cuda_fp16.h>
#include <math.h>
#include <stdint.h>

#define D_DIM 1024
#define H_DIM 2048
#define E_NUM 8
#define CAP   8192
#define N_TOK 8192
#define BM 128
#define BN 256
#define BK 64                            // halves per slab = 128 B rows

#define A_BYTES 16384                    // 128 rows x 128B
#define B_BYTES 32768                    // 256 rows x 128B
#define STAGE_BYTES (A_BYTES + B_BYTES)  // 49152
#define NSTAGE 4
#define SMEM_TOTAL (1024 + NSTAGE * STAGE_BYTES)  // 197632

// ---------------- device scratch ----------------
__device__ int    g_cnt[E_NUM];
__device__ int    g_off[E_NUM];
__device__ int    g_tok[E_NUM * CAP];
__device__ float  g_gate[E_NUM * CAP];
__device__ int    g_inv[N_TOK * 2];
__device__ float  g_imp[E_NUM];
__device__ float  g_ent;
__device__ __half g_xh[(size_t)N_TOK * D_DIM];            // x as half, k-permuted
__device__ __half g_hh[(size_t)N_TOK * 2 * H_DIM];        // h as half, k-permuted
__device__ __half g_yh[(size_t)N_TOK * 2 * D_DIM];        // gate*y as half
__device__ __half g_w1h[(size_t)E_NUM * H_DIM * D_DIM];   // [e][n=H][k'=D]
__device__ __half g_w2h[(size_t)E_NUM * D_DIM * H_DIM];   // [e][n=D][k'=H]

// k-group permutation: storage slot s holds source k = KORD[s]
__device__ __constant__ int KORD[16] = {0,1,8,9,2,3,10,11,4,5,12,13,6,7,14,15};
__device__ __forceinline__ int kslot(int r) {      // r = k & 15, even
    return (((r >> 1) & 3) << 2) + ((r >> 3) << 1);
}

// ---------------- helpers ----------------
__device__ __forceinline__ uint32_t smem_u32(const void* p) {
    uint32_t a;
    asm("{ .reg .u64 t; cvta.to.shared.u64 t, %1; cvt.u32.u64 %0, t; }" : "=r"(a) : "l"(p));
    return a;
}
#define CP16(dst, src) \
    asm volatile("cp.async.cg.shared.global [%0], [%1], 16;" :: "r"(dst), "l"(src))
#define CP_COMMIT()  asm volatile("cp.async.commit_group;" ::: "memory")
#define CP_WAIT(n)   asm volatile("cp.async.wait_group %0;" :: "n"(n) : "memory")

__device__ __forceinline__ void mma_f16(float* c, unsigned a0, unsigned a1,
                                        unsigned a2, unsigned a3,
                                        unsigned b0, unsigned b1) {
    asm volatile(
        "mma.sync.aligned.m16n8k16.row.col.f32.f16.f16.f32 "
        "{%0,%1,%2,%3}, {%4,%5,%6,%7}, {%8,%9}, {%0,%1,%2,%3};\n"
        : "+f"(c[0]), "+f"(c[1]), "+f"(c[2]), "+f"(c[3])
        : "r"(a0), "r"(a1), "r"(a2), "r"(a3), "r"(b0), "r"(b1));
}
__device__ __forceinline__ float gelu_exact(float v) {
    return 0.5f * v * (1.0f + erff(v * 0.70710678118654752440f));
}

// ---------------- shared bodies ----------------
// W[e][k][n] fp32 -> WT[e][n][k'] half, one 64x64 tile.
// Column XOR swizzle keyed on row>>4: conflict-free smem reads AND
// coalesced 128B global stores.
__device__ __forceinline__ void wtrans_body(const float* __restrict__ W,
                                            __half* __restrict__ WT,
                                            int K, int N, int nbi, int kbi, int e,
                                            float (*t)[68]) {
    int n0 = nbi * 64, k0 = kbi * 64;
    const float* Ws = W + (size_t)e * K * N + (size_t)k0 * N + n0;
    __half* Wd = WT + (size_t)e * N * K;
#pragma unroll
    for (int i = 0; i < 4; i++) {
        int idx = threadIdx.x + 256 * i;     // 0..1023
        int kr = idx >> 4, c4 = idx & 15;
        float4 v = *reinterpret_cast<const float4*>(Ws + (size_t)kr * N + c4 * 4);
        int cs = (c4 * 4) ^ (((kr >> 4) & 3) << 3);   // 8-multiple XOR: float4-safe
        *reinterpret_cast<float4*>(&t[kr][cs]) = v;
    }
    __syncthreads();
    int n = threadIdx.x >> 2, kg = (threadIdx.x & 3) * 16;
    __half hh[16];
#pragma unroll
    for (int s = 0; s < 16; s++) {
        int row = kg + KORD[s];
        hh[s] = __float2half(t[row][n ^ (((row >> 4) & 3) << 3)]);
    }
    __half* drow = Wd + (size_t)(n0 + n) * K + k0 + kg;
    *reinterpret_cast<uint4*>(drow)     = *reinterpret_cast<uint4*>(hh);
    *reinterpret_cast<uint4*>(drow + 8) = *reinterpret_cast<uint4*>(hh + 8);
}

// ---------------- prelude: router (+x->half) | W1 transpose ----------------
__global__ void prelude_k(const float* __restrict__ x,
                          const float* __restrict__ gW,
                          const float* __restrict__ gb,
                          const float* __restrict__ W1) {
    __shared__ __align__(16) char smbuf[32768];

    if (blockIdx.x >= 1024) {
        int lin = blockIdx.x - 1024;         // W1: N=H_DIM (32 tiles), K=D_DIM (16 tiles)
        wtrans_body(W1, g_w1h, D_DIM, H_DIM,
                    lin & 31, (lin >> 5) & 15, lin >> 9,
                    reinterpret_cast<float(*)[68]>(smbuf));
        return;
    }

    float4* sgW = reinterpret_cast<float4*>(smbuf);   // 32 KB, 16B-swizzled
    int tid = threadIdx.x;
    for (int s = tid; s < 2048; s += 256)
        sgW[s ^ ((s >> 3) & 7)] = reinterpret_cast<const float4*>(gW)[s];
    __syncthreads();

    int token = (blockIdx.x * blockDim.x + tid) >> 5;
    int lane  = tid & 31;
    const float* xr = x + (size_t)token * D_DIM;
    __half* xh = g_xh + (size_t)token * D_DIM;

    float acc[8] = {0.f,0.f,0.f,0.f,0.f,0.f,0.f,0.f};
#pragma unroll
    for (int i = 0; i < 8; i++) {
        int d = lane * 4 + 128 * i;
        float4 xv = *reinterpret_cast<const float4*>(xr + d);
        int base = d & ~15, r = d & 15;
        *reinterpret_cast<__half2*>(xh + base + kslot(r)) =
            __floats2half2_rn(xv.x, xv.y);
        *reinterpret_cast<__half2*>(xh + base + kslot(r + 2)) =
            __floats2half2_rn(xv.z, xv.w);
        float xs[4] = {xv.x, xv.y, xv.z, xv.w};
#pragma unroll
        for (int q = 0; q < 4; q++) {
            int s0 = (d + q) * 2;
            float4 wa = sgW[s0 ^ ((s0 >> 3) & 7)];
            int s1 = s0 + 1;
            float4 wb = sgW[s1 ^ ((s1 >> 3) & 7)];
            acc[0] += xs[q] * wa.x; acc[1] += xs[q] * wa.y;
            acc[2] += xs[q] * wa.z; acc[3] += xs[q] * wa.w;
            acc[4] += xs[q] * wb.x; acc[5] += xs[q] * wb.y;
            acc[6] += xs[q] * wb.z; acc[7] += xs[q] * wb.w;
        }
    }
#pragma unroll
    for (int e = 0; e < 8; e++)
#pragma unroll
        for (int o = 16; o; o >>= 1) acc[e] += __shfl_xor_sync(0xffffffffu, acc[e], o);
    if (lane) return;

    float lg[8];
#pragma unroll
    for (int e = 0; e < 8; e++) lg[e] = acc[e] + gb[e];
    float mx = lg[0];
#pragma unroll
    for (int e = 1; e < 8; e++) mx = fmaxf(mx, lg[e]);
    float p[8], Z = 0.f;
#pragma unroll
    for (int e = 0; e < 8; e++) { p[e] = expf(lg[e] - mx); Z += p[e]; }
    float ent = 0.f;
#pragma unroll
    for (int e = 0; e < 8; e++) {
        p[e] /= Z;
        ent -= p[e] * logf(p[e] + 1e-8f);
        atomicAdd(&g_imp[e], p[e]);
    }
    atomicAdd(&g_ent, ent);

    int e0 = 0;
#pragma unroll
    for (int e = 1; e < 8; e++) if (lg[e] > lg[e0]) e0 = e;
    int e1 = -1;
#pragma unroll
    for (int e = 0; e < 8; e++) if (e != e0 && (e1 < 0 || lg[e] > lg[e1])) e1 = e;

    float dlt = expf(lg[e1] - lg[e0]);
    float g0 = 1.0f / (1.0f + dlt);
    float g1 = dlt / (1.0f + dlt);

    int s0 = atomicAdd(&g_cnt[e0], 1);
    g_tok[e0 * CAP + s0] = token; g_gate[e0 * CAP + s0] = g0;
    int s1 = atomicAdd(&g_cnt[e1], 1);
    g_tok[e1 * CAP + s1] = token; g_gate[e1 * CAP + s1] = g1;
    g_inv[token * 2 + 0] = e0 * CAP + s0;
    g_inv[token * 2 + 1] = e1 * CAP + s1;
}

__global__ void tail_k(float* __restrict__ out_tail) {
    if (threadIdx.x != 0 || blockIdx.x != 0) return;
    int off = 0;
    float loadv[8], impv[8];
    for (int e = 0; e < 8; e++) { g_off[e] = off; off += g_cnt[e]; }
    for (int e = 0; e < 8; e++) {
        loadv[e] = (float)g_cnt[e] / (float)N_TOK;
        impv[e]  = g_imp[e] / (float)N_TOK;
    }
    float bal = 0.f, util = 0.f;
    for (int e = 0; e < 8; e++) bal += impv[e] * loadv[e];
    bal *= (float)E_NUM;
    for (int e = 0; e < 8; e++) util -= loadv[e] * logf(loadv[e] + 1e-8f);
    out_tail[0] = bal;
    out_tail[1] = g_ent / (float)N_TOK;
    out_tail[2] = util;
    for (int e = 0; e < 8; e++) out_tail[3 + e]  = loadv[e];
    for (int e = 0; e < 8; e++) out_tail[11 + e] = impv[e];
}

// ---------------- fp16 pipelined grouped GEMM (128x256, warp 64x64, BK=64) ----------------
// MODE 0: A = gather(g_xh) [K=1024], B=g_w1h, bias+gelu -> g_hh (half, permuted)
//         blocks with blockIdx.y >= 64 instead transpose W2 -> g_w2h
// MODE 1: A = g_hh [K=2048], B=g_w2h, gate*(bias+c) -> g_yh (half)
template <int MODE>
__global__ void __launch_bounds__(256, 1)
gemm_h(const float* __restrict__ bias, const float* __restrict__ W2) {
    constexpr int Kdim  = (MODE == 0) ? D_DIM : H_DIM;
    constexpr int Ncols = (MODE == 0) ? H_DIM : D_DIM;
    constexpr int NS    = Kdim / BK;

    extern __shared__ char smem[];

    if (MODE == 0 && blockIdx.y >= 64) {
        // W2 transpose: N=D_DIM (16 tiles), K=H_DIM (32 tiles)
        int lin = blockIdx.x + 8 * (blockIdx.y - 64) + 512 * blockIdx.z;
        wtrans_body(W2, g_w2h, H_DIM, D_DIM,
                    lin & 15, (lin >> 4) & 31, lin >> 9,
                    reinterpret_cast<float(*)[68]>(smem));
        return;
    }

    const int e = blockIdx.z;
    const int cnt = g_cnt[e];
    const int m_base = blockIdx.y * BM;
    if (m_base >= cnt) return;
    const int n_base = blockIdx.x * BN;
    const int hoff = g_off[e];

    const int tid = threadIdx.x, wid = tid >> 5, lane = tid & 31;
    const int g = lane >> 2, tig = lane & 3;
    const int wm = (wid & 1) * 64;
    const int wn = (wid >> 1) * 64;
    const uint32_t sb = smem_u32(smem);
    float* sBias = (float*)smem;

    sBias[tid] = bias[(size_t)e * Ncols + n_base + tid];

    // ---- cp.async assignments ----
    const int cch = tid & 7;          // 16B chunk (8 halves) within 128B row
    const int r0  = tid >> 3;         // base row 0..31
    const __half* Ab = (MODE == 0) ? (const __half*)g_xh : (const __half*)g_hh;
    const __half* Wb = (MODE == 0) ? (const __half*)g_w1h : (const __half*)g_w2h;

    const __half* aSrc[4];
#pragma unroll
    for (int i = 0; i < 4; i++) {
        int am = m_base + r0 + 32 * i;
        if (am >= cnt) am = cnt - 1;
        size_t row = (MODE == 0) ? (size_t)g_tok[e * CAP + am] : (size_t)(hoff + am);
        aSrc[i] = Ab + row * Kdim + cch * 8;
    }
    const __half* bSrc = Wb + ((size_t)e * Ncols + n_base + r0) * Kdim + cch * 8;

    const uint32_t swz = (uint32_t)((cch ^ (r0 & 7)) << 4);
    const uint32_t aDst = sb + 1024 + r0 * 128 + swz;
    const uint32_t bDst = sb + 1024 + A_BYTES + r0 * 128 + swz;

    float c[4][8][4];
#pragma unroll
    for (int i = 0; i < 4; i++)
#pragma unroll
        for (int j = 0; j < 8; j++)
#pragma unroll
            for (int r = 0; r < 4; r++) c[i][j][r] = 0.f;

    auto issue = [&](int s) {
        if (s < NS) {
            const int kb = s * BK;
            const uint32_t so = (uint32_t)((s & (NSTAGE - 1)) * STAGE_BYTES);
#pragma unroll
            for (int i = 0; i < 4; i++)
                CP16(aDst + so + i * 4096, aSrc[i] + kb);
#pragma unroll
            for (int i = 0; i < 8; i++)
                CP16(bDst + so + i * 4096, bSrc + (size_t)(32 * i) * Kdim + kb);
        }
        CP_COMMIT();
    };

    issue(0); issue(1); issue(2);

    const int aRow = (wm + g) * 128;
    const int bRow = A_BYTES + (wn + g) * 128;

    for (int s = 0; s < NS; s++) {
        CP_WAIT(2);
        __syncthreads();
        issue(s + 3);

        const char* stg = smem + 1024 + (s & (NSTAGE - 1)) * STAGE_BYTES;
#pragma unroll
        for (int kx = 0; kx < 4; kx++) {
            const int off = (((2 * kx + (tig >> 1)) ^ g) << 4) + 8 * (tig & 1);
            uint2 ua0[4], ua1[4], ub[8];
#pragma unroll
            for (int i = 0; i < 4; i++) {
                ua0[i] = *(const uint2*)(stg + aRow + i * 2048 + off);
                ua1[i] = *(const uint2*)(stg + aRow + i * 2048 + 1024 + off);
            }
#pragma unroll
            for (int j = 0; j < 8; j++)
                ub[j] = *(const uint2*)(stg + bRow + j * 1024 + off);
#pragma unroll
            for (int i = 0; i < 4; i++)
#pragma unroll
                for (int j = 0; j < 8; j++)
                    mma_f16(c[i][j], ua0[i].x, ua1[i].x, ua0[i].y, ua1[i].y,
                            ub[j].x, ub[j].y);
        }
    }

    // ---- epilogue ----
#pragma unroll
    for (int i = 0; i < 4; i++) {
#pragma unroll
        for (int half = 0; half < 2; half++) {
            int mrow = m_base + wm + 16 * i + g + half * 8;
            if (mrow >= cnt) continue;
            if (MODE == 0) {
                __half* hp = g_hh + (size_t)(hoff + mrow) * H_DIM + n_base;
#pragma unroll
                for (int j = 0; j < 8; j++) {
                    int col = wn + j * 8 + tig * 2;
                    float v0 = c[i][j][half * 2 + 0] + sBias[col];
                    float v1 = c[i][j][half * 2 + 1] + sBias[col + 1];
                    int col2 = (col & ~15) + kslot(col & 15);   // permuted store
                    *reinterpret_cast<__half2*>(hp + col2) =
                        __floats2half2_rn(gelu_exact(v0), gelu_exact(v1));
                }
            } else {
                float gate = g_gate[e * CAP + mrow];
                __half* yp = g_yh + (size_t)(hoff + mrow) * D_DIM + n_base;
#pragma unroll
                for (int j = 0; j < 8; j++) {
                    int col = wn + j * 8 + tig * 2;
                    float v0 = gate * (c[i][j][half * 2 + 0] + sBias[col]);
                    float v1 = gate * (c[i][j][half * 2 + 1] + sBias[col + 1]);
                    *reinterpret_cast<__half2*>(yp + col) = __floats2half2_rn(v0, v1);
                }
            }
        }
    }
}

// ---------------- LayerNorm (y pre-gated, fp16); resets counters for next replay ----------------
__global__ void ln_k(const float* __restrict__ x,
                     const float* __restrict__ gamma,
                     const float* __restrict__ beta,
                     float* __restrict__ out) {
    int t = blockIdx.x;
    int tid = threadIdx.x;
    int lane = tid & 31, wid = tid >> 5;

    // fold reset_k in here: counters are no longer read this launch;
    // block 0 re-zeros them for the next graph replay (first call relies
    // on zero-initialized __device__ globals).
    if (t == 0 && wid == 0) {
        if (lane < E_NUM) { g_cnt[lane] = 0; g_imp[lane] = 0.0f; }
        if (lane == 0)    g_ent = 0.0f;
    }

    int i0 = g_inv[t * 2 + 0], i1 = g_inv[t * 2 + 1];
    size_t r0 = (size_t)(g_off[i0 >> 13] + (i0 & (CAP - 1)));
    size_t r1 = (size_t)(g_off[i1 >> 13] + (i1 & (CAP - 1)));
    const __half* y0 = g_yh + r0 * D_DIM;
    const __half* y1 = g_yh + r1 * D_DIM;
    const float* xr = x + (size_t)t * D_DIM;

    int c = tid * 4;
    float4 xv = *reinterpret_cast<const float4*>(xr + c);
    __half2 a01 = *reinterpret_cast<const __half2*>(y0 + c);
    __half2 a23 = *reinterpret_cast<const __half2*>(y0 + c + 2);
    __half2 b01 = *reinterpret_cast<const __half2*>(y1 + c);
    __half2 b23 = *reinterpret_cast<const __half2*>(y1 + c + 2);
    float2 fa01 = __half22float2(a01), fa23 = __half22float2(a23);
    float2 fb01 = __half22float2(b01), fb23 = __half22float2(b23);
    float z0 = xv.x + fa01.x + fb01.x;
    float z1 = xv.y + fa01.y + fb01.y;
    float z2 = xv.z + fa23.x + fb23.x;
    float z3 = xv.w + fa23.y + fb23.y;

    float s  = z0 + z1 + z2 + z3;
    float sq = z0 * z0 + z1 * z1 + z2 * z2 + z3 * z3;
#pragma unroll
    for (int o = 16; o; o >>= 1) {
        s  += __shfl_xor_sync(0xffffffffu, s, o);
        sq += __shfl_xor_sync(0xffffffffu, sq, o);
    }
    __shared__ float ws[8], wq[8];
    if (lane == 0) { ws[wid] = s; wq[wid] = sq; }
    __syncthreads();
    if (wid == 0) {
        float s2 = (lane < 8) ? ws[lane] : 0.f;
        float q2 = (lane < 8) ? wq[lane] : 0.f;
#pragma unroll
        for (int o = 4; o; o >>= 1) {
            s2 += __shfl_xor_sync(0xffffffffu, s2, o);
            q2 += __shfl_xor_sync(0xffffffffu, q2, o);
        }
        if (lane == 0) { ws[0] = s2; wq[0] = q2; }
    }
    __syncthreads();
    float mu  = ws[0] * (1.0f / D_DIM);
    float var = wq[0] * (1.0f / D_DIM) - mu * mu;
    float inv = rsqrtf(var + 1e-5f);

    float4 gm = *reinterpret_cast<const float4*>(gamma + c);
    float4 bt = *reinterpret_cast<const float4*>(beta + c);
    float4 o;
    o.x = (z0 - mu) * inv * gm.x + bt.x;
    o.y = (z1 - mu) * inv * gm.y + bt.y;
    o.z = (z2 - mu) * inv * gm.z + bt.z;
    o.w = (z3 - mu) * inv * gm.w + bt.w;
    *reinterpret_cast<float4*>(out + (size_t)t * D_DIM + c) = o;
}

// ---------------- launch ----------------
extern "C" void kernel_launch(void* const* d_in, const int* in_sizes, int n_in,
                              void* d_out, int out_size) {
    (void)in_sizes; (void)n_in; (void)out_size;
    const float* x     = (const float*)d_in[0];
    const float* gW    = (const float*)d_in[1];
    const float* gb    = (const float*)d_in[2];
    const float* W1    = (const float*)d_in[3];
    const float* b1    = (const float*)d_in[4];
    const float* W2    = (const float*)d_in[5];
    const float* b2    = (const float*)d_in[6];
    const float* gamma = (const float*)d_in[7];
    const float* beta  = (const float*)d_in[8];
    float* out = (float*)d_out;

    cudaFuncSetAttribute((const void*)gemm_h<0>,
                         cudaFuncAttributeMaxDynamicSharedMemorySize, SMEM_TOTAL);
    cudaFuncSetAttribute((const void*)gemm_h<1>,
                         cudaFuncAttributeMaxDynamicSharedMemorySize, SMEM_TOTAL);

    prelude_k<<<1024 + 4096, 256>>>(x, gW, gb, W1);      // router + W1 transpose
    tail_k<<<1, 1>>>(out + (size_t)N_TOK * D_DIM);
    // GEMM1 (by<64) + W2 transpose (by>=64)
    gemm_h<0><<<dim3(H_DIM / BN, 128, E_NUM), 256, SMEM_TOTAL>>>(b1, W2);
    gemm_h<1><<<dim3(D_DIM / BN, CAP / BM, E_NUM), 256, SMEM_TOTAL>>>(b2, nullptr);
    ln_k<<<N_TOK, 256>>>(x, gamma, beta, out);           // + counter reset for next replay
}

// round 14
// speedup vs baseline: 1.1220x; 1.0033x over previous
#include <cuda_runtime.h>
#include <cuda_fp16.h>
#include <math.h>
#include <stdint.h>

#define D_DIM 1024
#define H_DIM 2048
#define E_NUM 8
#define CAP   8192
#define N_TOK 8192
#define BM 128
#define BN 256
#define BK 64                            // halves per slab = 128 B rows

#define A_BYTES 16384                    // 128 rows x 128B
#define B_BYTES 32768                    // 256 rows x 128B
#define STAGE_BYTES (A_BYTES + B_BYTES)  // 49152
#define NSTAGE 4
#define SMEM_TOTAL (1024 + NSTAGE * STAGE_BYTES)  // 197632

// ---------------- device scratch ----------------
__device__ int    g_cnt[E_NUM];
__device__ int    g_off[E_NUM];
__device__ int    g_tok[E_NUM * CAP];
__device__ float  g_gate[E_NUM * CAP];
__device__ int    g_inv[N_TOK * 2];
__device__ float  g_imp[E_NUM];
__device__ float  g_ent;
__device__ __half g_xh[(size_t)N_TOK * D_DIM];            // x as half, k-permuted
__device__ __half g_hh[(size_t)N_TOK * 2 * H_DIM];        // h as half, k-permuted
__device__ __half g_yh[(size_t)N_TOK * 2 * D_DIM];        // gate*y as half
__device__ __half g_w1h[(size_t)E_NUM * H_DIM * D_DIM];   // [e][n=H][k'=D]
__device__ __half g_w2h[(size_t)E_NUM * D_DIM * H_DIM];   // [e][n=D][k'=H]

// k-group permutation: storage slot s holds source k = KORD[s]
__device__ __constant__ int KORD[16] = {0,1,8,9,2,3,10,11,4,5,12,13,6,7,14,15};
__device__ __forceinline__ int kslot(int r) {      // r = k & 15, even
    return (((r >> 1) & 3) << 2) + ((r >> 3) << 1);
}

// ---------------- helpers ----------------
__device__ __forceinline__ uint32_t smem_u32(const void* p) {
    uint32_t a;
    asm("{ .reg .u64 t; cvta.to.shared.u64 t, %1; cvt.u32.u64 %0, t; }" : "=r"(a) : "l"(p));
    return a;
}
#define CP16(dst, src) \
    asm volatile("cp.async.cg.shared.global [%0], [%1], 16;" :: "r"(dst), "l"(src))
#define CP_COMMIT()  asm volatile("cp.async.commit_group;" ::: "memory")
#define CP_WAIT(n)   asm volatile("cp.async.wait_group %0;" :: "n"(n) : "memory")

__device__ __forceinline__ void mma_f16(float* c, unsigned a0, unsigned a1,
                                        unsigned a2, unsigned a3,
                                        unsigned b0, unsigned b1) {
    asm volatile(
        "mma.sync.aligned.m16n8k16.row.col.f32.f16.f16.f32 "
        "{%0,%1,%2,%3}, {%4,%5,%6,%7}, {%8,%9}, {%0,%1,%2,%3};\n"
        : "+f"(c[0]), "+f"(c[1]), "+f"(c[2]), "+f"(c[3])
        : "r"(a0), "r"(a1), "r"(a2), "r"(a3), "r"(b0), "r"(b1));
}
__device__ __forceinline__ float gelu_exact(float v) {
    return 0.5f * v * (1.0f + erff(v * 0.70710678118654752440f));
}

// ---------------- shared bodies ----------------
// W[e][k][n] fp32 -> WT[e][n][k'] half, one 64x64 tile.
// Column XOR swizzle keyed on row>>4: conflict-free smem reads AND
// coalesced 128B global stores.
__device__ __forceinline__ void wtrans_body(const float* __restrict__ W,
                                            __half* __restrict__ WT,
                                            int K, int N, int nbi, int kbi, int e,
                                            float (*t)[68]) {
    int n0 = nbi * 64, k0 = kbi * 64;
    const float* Ws = W + (size_t)e * K * N + (size_t)k0 * N + n0;
    __half* Wd = WT + (size_t)e * N * K;
#pragma unroll
    for (int i = 0; i < 4; i++) {
        int idx = threadIdx.x + 256 * i;     // 0..1023
        int kr = idx >> 4, c4 = idx & 15;
        float4 v = *reinterpret_cast<const float4*>(Ws + (size_t)kr * N + c4 * 4);
        int cs = (c4 * 4) ^ (((kr >> 4) & 3) << 3);   // 8-multiple XOR: float4-safe
        *reinterpret_cast<float4*>(&t[kr][cs]) = v;
    }
    __syncthreads();
    int n = threadIdx.x >> 2, kg = (threadIdx.x & 3) * 16;
    __half hh[16];
#pragma unroll
    for (int s = 0; s < 16; s++) {
        int row = kg + KORD[s];
        hh[s] = __float2half(t[row][n ^ (((row >> 4) & 3) << 3)]);
    }
    __half* drow = Wd + (size_t)(n0 + n) * K + k0 + kg;
    *reinterpret_cast<uint4*>(drow)     = *reinterpret_cast<uint4*>(hh);
    *reinterpret_cast<uint4*>(drow + 8) = *reinterpret_cast<uint4*>(hh + 8);
}

// ---------------- prelude: router (+x->half) | W1 transpose ----------------
__global__ void prelude_k(const float* __restrict__ x,
                          const float* __restrict__ gW,
                          const float* __restrict__ gb,
                          const float* __restrict__ W1) {
    __shared__ __align__(16) char smbuf[32768];

    if (blockIdx.x >= 1024) {
        int lin = blockIdx.x - 1024;         // W1: N=H_DIM (32 tiles), K=D_DIM (16 tiles)
        wtrans_body(W1, g_w1h, D_DIM, H_DIM,
                    lin & 31, (lin >> 5) & 15, lin >> 9,
                    reinterpret_cast<float(*)[68]>(smbuf));
        return;
    }

    float4* sgW = reinterpret_cast<float4*>(smbuf);   // 32 KB, 16B-swizzled
    int tid = threadIdx.x;
    for (int s = tid; s < 2048; s += 256)
        sgW[s ^ ((s >> 3) & 7)] = reinterpret_cast<const float4*>(gW)[s];
    __syncthreads();

    int token = (blockIdx.x * blockDim.x + tid) >> 5;
    int lane  = tid & 31;
    const float* xr = x + (size_t)token * D_DIM;
    __half* xh = g_xh + (size_t)token * D_DIM;

    float acc[8] = {0.f,0.f,0.f,0.f,0.f,0.f,0.f,0.f};
#pragma unroll
    for (int i = 0; i < 8; i++) {
        int d = lane * 4 + 128 * i;
        float4 xv = *reinterpret_cast<const float4*>(xr + d);
        int base = d & ~15, r = d & 15;
        *reinterpret_cast<__half2*>(xh + base + kslot(r)) =
            __floats2half2_rn(xv.x, xv.y);
        *reinterpret_cast<__half2*>(xh + base + kslot(r + 2)) =
            __floats2half2_rn(xv.z, xv.w);
        float xs[4] = {xv.x, xv.y, xv.z, xv.w};
#pragma unroll
        for (int q = 0; q < 4; q++) {
            int s0 = (d + q) * 2;
            float4 wa = sgW[s0 ^ ((s0 >> 3) & 7)];
            int s1 = s0 + 1;
            float4 wb = sgW[s1 ^ ((s1 >> 3) & 7)];
            acc[0] += xs[q] * wa.x; acc[1] += xs[q] * wa.y;
            acc[2] += xs[q] * wa.z; acc[3] += xs[q] * wa.w;
            acc[4] += xs[q] * wb.x; acc[5] += xs[q] * wb.y;
            acc[6] += xs[q] * wb.z; acc[7] += xs[q] * wb.w;
        }
    }
#pragma unroll
    for (int e = 0; e < 8; e++)
#pragma unroll
        for (int o = 16; o; o >>= 1) acc[e] += __shfl_xor_sync(0xffffffffu, acc[e], o);
    if (lane) return;

    float lg[8];
#pragma unroll
    for (int e = 0; e < 8; e++) lg[e] = acc[e] + gb[e];
    float mx = lg[0];
#pragma unroll
    for (int e = 1; e < 8; e++) mx = fmaxf(mx, lg[e]);
    float p[8], Z = 0.f;
#pragma unroll
    for (int e = 0; e < 8; e++) { p[e] = expf(lg[e] - mx); Z += p[e]; }
    float ent = 0.f;
#pragma unroll
    for (int e = 0; e < 8; e++) {
        p[e] /= Z;
        ent -= p[e] * logf(p[e] + 1e-8f);
        atomicAdd(&g_imp[e], p[e]);
    }
    atomicAdd(&g_ent, ent);

    int e0 = 0;
#pragma unroll
    for (int e = 1; e < 8; e++) if (lg[e] > lg[e0]) e0 = e;
    int e1 = -1;
#pragma unroll
    for (int e = 0; e < 8; e++) if (e != e0 && (e1 < 0 || lg[e] > lg[e1])) e1 = e;

    float dlt = expf(lg[e1] - lg[e0]);
    float g0 = 1.0f / (1.0f + dlt);
    float g1 = dlt / (1.0f + dlt);

    int s0 = atomicAdd(&g_cnt[e0], 1);
    g_tok[e0 * CAP + s0] = token; g_gate[e0 * CAP + s0] = g0;
    int s1 = atomicAdd(&g_cnt[e1], 1);
    g_tok[e1 * CAP + s1] = token; g_gate[e1 * CAP + s1] = g1;
    g_inv[token * 2 + 0] = e0 * CAP + s0;
    g_inv[token * 2 + 1] = e1 * CAP + s1;
}

// ---------------- fp16 pipelined grouped GEMM (128x256, warp 64x64, BK=64) ----------------
// MODE 0: A = gather(g_xh) [K=1024], B=g_w1h, bias+gelu -> g_hh (half, permuted)
//         blocks with blockIdx.y >= 64 instead transpose W2 -> g_w2h;
//         the lin==0 transpose block also computes g_off + the 19 tail outputs
// MODE 1: A = g_hh [K=2048], B=g_w2h, gate*(bias+c) -> g_yh (half)
template <int MODE>
__global__ void __launch_bounds__(256, 1)
gemm_h(const float* __restrict__ bias, const float* __restrict__ W2,
       float* __restrict__ out_tail) {
    constexpr int Kdim  = (MODE == 0) ? D_DIM : H_DIM;
    constexpr int Ncols = (MODE == 0) ? H_DIM : D_DIM;
    constexpr int NS    = Kdim / BK;

    extern __shared__ char smem[];

    if (MODE == 0 && blockIdx.y >= 64) {
        // W2 transpose: N=D_DIM (16 tiles), K=H_DIM (32 tiles)
        int lin = blockIdx.x + 8 * (blockIdx.y - 64) + 512 * blockIdx.z;
        wtrans_body(W2, g_w2h, H_DIM, D_DIM,
                    lin & 15, (lin >> 4) & 31, lin >> 9,
                    reinterpret_cast<float(*)[68]>(smem));
        // fold the former tail_k into one block (counters final after prelude;
        // g_off is read only by gemm_h<1>/ln_k, which launch after this kernel)
        if (lin == 0 && threadIdx.x == 0) {
            int off = 0;
            float loadv[8], impv[8];
            for (int e = 0; e < 8; e++) { g_off[e] = off; off += g_cnt[e]; }
            for (int e = 0; e < 8; e++) {
                loadv[e] = (float)g_cnt[e] / (float)N_TOK;
                impv[e]  = g_imp[e] / (float)N_TOK;
            }
            float bal = 0.f, util = 0.f;
            for (int e = 0; e < 8; e++) bal += impv[e] * loadv[e];
            bal *= (float)E_NUM;
            for (int e = 0; e < 8; e++) util -= loadv[e] * logf(loadv[e] + 1e-8f);
            out_tail[0] = bal;
            out_tail[1] = g_ent / (float)N_TOK;
            out_tail[2] = util;
            for (int e = 0; e < 8; e++) out_tail[3 + e]  = loadv[e];
            for (int e = 0; e < 8; e++) out_tail[11 + e] = impv[e];
        }
        return;
    }

    const int e = blockIdx.z;
    const int cnt = g_cnt[e];
    const int m_base = blockIdx.y * BM;
    if (m_base >= cnt) return;
    const int n_base = blockIdx.x * BN;
    // hoff: MODE 0 computes the prefix locally (g_off not yet written);
    // MODE 1 reads g_off (written during the MODE-0 kernel).
    int hoff;
    if (MODE == 0) {
        hoff = 0;
        for (int i = 0; i < e; i++) hoff += g_cnt[i];
    } else {
        hoff = g_off[e];
    }

    const int tid = threadIdx.x, wid = tid >> 5, lane = tid & 31;
    const int g = lane >> 2, tig = lane & 3;
    const int wm = (wid & 1) * 64;
    const int wn = (wid >> 1) * 64;
    const uint32_t sb = smem_u32(smem);
    float* sBias = (float*)smem;

    sBias[tid] = bias[(size_t)e * Ncols + n_base + tid];

    // ---- cp.async assignments ----
    const int cch = tid & 7;          // 16B chunk (8 halves) within 128B row
    const int r0  = tid >> 3;         // base row 0..31
    const __half* Ab = (MODE == 0) ? (const __half*)g_xh : (const __half*)g_hh;
    const __half* Wb = (MODE == 0) ? (const __half*)g_w1h : (const __half*)g_w2h;

    const __half* aSrc[4];
#pragma unroll
    for (int i = 0; i < 4; i++) {
        int am = m_base + r0 + 32 * i;
        if (am >= cnt) am = cnt - 1;
        size_t row = (MODE == 0) ? (size_t)g_tok[e * CAP + am] : (size_t)(hoff + am);
        aSrc[i] = Ab + row * Kdim + cch * 8;
    }
    const __half* bSrc = Wb + ((size_t)e * Ncols + n_base + r0) * Kdim + cch * 8;

    const uint32_t swz = (uint32_t)((cch ^ (r0 & 7)) << 4);
    const uint32_t aDst = sb + 1024 + r0 * 128 + swz;
    const uint32_t bDst = sb + 1024 + A_BYTES + r0 * 128 + swz;

    float c[4][8][4];
#pragma unroll
    for (int i = 0; i < 4; i++)
#pragma unroll
        for (int j = 0; j < 8; j++)
#pragma unroll
            for (int r = 0; r < 4; r++) c[i][j][r] = 0.f;

    auto issue = [&](int s) {
        if (s < NS) {
            const int kb = s * BK;
            const uint32_t so = (uint32_t)((s & (NSTAGE - 1)) * STAGE_BYTES);
#pragma unroll
            for (int i = 0; i < 4; i++)
                CP16(aDst + so + i * 4096, aSrc[i] + kb);
#pragma unroll
            for (int i = 0; i < 8; i++)
                CP16(bDst + so + i * 4096, bSrc + (size_t)(32 * i) * Kdim + kb);
        }
        CP_COMMIT();
    };

    issue(0); issue(1); issue(2);

    const int aRow = (wm + g) * 128;
    const int bRow = A_BYTES + (wn + g) * 128;

    for (int s = 0; s < NS; s++) {
        CP_WAIT(2);
        __syncthreads();
        issue(s + 3);

        const char* stg = smem + 1024 + (s & (NSTAGE - 1)) * STAGE_BYTES;
#pragma unroll
        for (int kx = 0; kx < 4; kx++) {
            const int off = (((2 * kx + (tig >> 1)) ^ g) << 4) + 8 * (tig & 1);
            uint2 ua0[4], ua1[4], ub[8];
#pragma unroll
            for (int i = 0; i < 4; i++) {
                ua0[i] = *(const uint2*)(stg + aRow + i * 2048 + off);
                ua1[i] = *(const uint2*)(stg + aRow + i * 2048 + 1024 + off);
            }
#pragma unroll
            for (int j = 0; j < 8; j++)
                ub[j] = *(const uint2*)(stg + bRow + j * 1024 + off);
#pragma unroll
            for (int i = 0; i < 4; i++)
#pragma unroll
                for (int j = 0; j < 8; j++)
                    mma_f16(c[i][j], ua0[i].x, ua1[i].x, ua0[i].y, ua1[i].y,
                            ub[j].x, ub[j].y);
        }
    }

    // ---- epilogue ----
#pragma unroll
    for (int i = 0; i < 4; i++) {
#pragma unroll
        for (int half = 0; half < 2; half++) {
            int mrow = m_base + wm + 16 * i + g + half * 8;
            if (mrow >= cnt) continue;
            if (MODE == 0) {
                __half* hp = g_hh + (size_t)(hoff + mrow) * H_DIM + n_base;
#pragma unroll
                for (int j = 0; j < 8; j++) {
                    int col = wn + j * 8 + tig * 2;
                    float v0 = c[i][j][half * 2 + 0] + sBias[col];
                    float v1 = c[i][j][half * 2 + 1] + sBias[col + 1];
                    int col2 = (col & ~15) + kslot(col & 15);   // permuted store
                    *reinterpret_cast<__half2*>(hp + col2) =
                        __floats2half2_rn(gelu_exact(v0), gelu_exact(v1));
                }
            } else {
                float gate = g_gate[e * CAP + mrow];
                __half* yp = g_yh + (size_t)(hoff + mrow) * D_DIM + n_base;
#pragma unroll
                for (int j = 0; j < 8; j++) {
                    int col = wn + j * 8 + tig * 2;
                    float v0 = gate * (c[i][j][half * 2 + 0] + sBias[col]);
                    float v1 = gate * (c[i][j][half * 2 + 1] + sBias[col + 1]);
                    *reinterpret_cast<__half2*>(yp + col) = __floats2half2_rn(v0, v1);
                }
            }
        }
    }
}

// ---------------- LayerNorm (y pre-gated, fp16); resets counters for next replay ----------------
__global__ void ln_k(const float* __restrict__ x,
                     const float* __restrict__ gamma,
                     const float* __restrict__ beta,
                     float* __restrict__ out) {
    int t = blockIdx.x;
    int tid = threadIdx.x;
    int lane = tid & 31, wid = tid >> 5;

    // counters are no longer read this launch; block 0 re-zeros them for the
    // next graph replay (first call relies on zero-initialized globals).
    if (t == 0 && wid == 0) {
        if (lane < E_NUM) { g_cnt[lane] = 0; g_imp[lane] = 0.0f; }
        if (lane == 0)    g_ent = 0.0f;
    }

    int i0 = g_inv[t * 2 + 0], i1 = g_inv[t * 2 + 1];
    size_t r0 = (size_t)(g_off[i0 >> 13] + (i0 & (CAP - 1)));
    size_t r1 = (size_t)(g_off[i1 >> 13] + (i1 & (CAP - 1)));
    const __half* y0 = g_yh + r0 * D_DIM;
    const __half* y1 = g_yh + r1 * D_DIM;
    const float* xr = x + (size_t)t * D_DIM;

    int c = tid * 4;
    float4 xv = *reinterpret_cast<const float4*>(xr + c);
    __half2 a01 = *reinterpret_cast<const __half2*>(y0 + c);
    __half2 a23 = *reinterpret_cast<const __half2*>(y0 + c + 2);
    __half2 b01 = *reinterpret_cast<const __half2*>(y1 + c);
    __half2 b23 = *reinterpret_cast<const __half2*>(y1 + c + 2);
    float2 fa01 = __half22float2(a01), fa23 = __half22float2(a23);
    float2 fb01 = __half22float2(b01), fb23 = __half22float2(b23);
    float z0 = xv.x + fa01.x + fb01.x;
    float z1 = xv.y + fa01.y + fb01.y;
    float z2 = xv.z + fa23.x + fb23.x;
    float z3 = xv.w + fa23.y + fb23.y;

    float s  = z0 + z1 + z2 + z3;
    float sq = z0 * z0 + z1 * z1 + z2 * z2 + z3 * z3;
#pragma unroll
    for (int o = 16; o; o >>= 1) {
        s  += __shfl_xor_sync(0xffffffffu, s, o);
        sq += __shfl_xor_sync(0xffffffffu, sq, o);
    }
    __shared__ float ws[8], wq[8];
    if (lane == 0) { ws[wid] = s; wq[wid] = sq; }
    __syncthreads();
    if (wid == 0) {
        float s2 = (lane < 8) ? ws[lane] : 0.f;
        float q2 = (lane < 8) ? wq[lane] : 0.f;
#pragma unroll
        for (int o = 4; o; o >>= 1) {
            s2 += __shfl_xor_sync(0xffffffffu, s2, o);
            q2 += __shfl_xor_sync(0xffffffffu, q2, o);
        }
        if (lane == 0) { ws[0] = s2; wq[0] = q2; }
    }
    __syncthreads();
    float mu  = ws[0] * (1.0f / D_DIM);
    float var = wq[0] * (1.0f / D_DIM) - mu * mu;
    float inv = rsqrtf(var + 1e-5f);

    float4 gm = *reinterpret_cast<const float4*>(gamma + c);
    float4 bt = *reinterpret_cast<const float4*>(beta + c);
    float4 o;
    o.x = (z0 - mu) * inv * gm.x + bt.x;
    o.y = (z1 - mu) * inv * gm.y + bt.y;
    o.z = (z2 - mu) * inv * gm.z + bt.z;
    o.w = (z3 - mu) * inv * gm.w + bt.w;
    *reinterpret_cast<float4*>(out + (size_t)t * D_DIM + c) = o;
}

// ---------------- launch ----------------
extern "C" void kernel_launch(void* const* d_in, const int* in_sizes, int n_in,
                              void* d_out, int out_size) {
    (void)in_sizes; (void)n_in; (void)out_size;
    const float* x     = (const float*)d_in[0];
    const float* gW    = (const float*)d_in[1];
    const float* gb    = (const float*)d_in[2];
    const float* W1    = (const float*)d_in[3];
    const float* b1    = (const float*)d_in[4];
    const float* W2    = (const float*)d_in[5];
    const float* b2    = (const float*)d_in[6];
    const float* gamma = (const float*)d_in[7];
    const float* beta  = (const float*)d_in[8];
    float* out = (float*)d_out;
    float* out_tail = out + (size_t)N_TOK * D_DIM;

    cudaFuncSetAttribute((const void*)gemm_h<0>,
                         cudaFuncAttributeMaxDynamicSharedMemorySize, SMEM_TOTAL);
    cudaFuncSetAttribute((const void*)gemm_h<1>,
                         cudaFuncAttributeMaxDynamicSharedMemorySize, SMEM_TOTAL);

    prelude_k<<<1024 + 4096, 256>>>(x, gW, gb, W1);      // router + W1 transpose
    // GEMM1 (by<64) + W2 transpose (by>=64) + tail outputs (lin==0 block)
    gemm_h<0><<<dim3(H_DIM / BN, 128, E_NUM), 256, SMEM_TOTAL>>>(b1, W2, out_tail);
    gemm_h<1><<<dim3(D_DIM / BN, CAP / BM, E_NUM), 256, SMEM_TOTAL>>>(b2, nullptr, nullptr);
    ln_k<<<N_TOK, 256>>>(x, gamma, beta, out);           // + counter reset for next replay
}

// round 15
// speedup vs baseline: 1.2560x; 1.1194x over previous
#include <cuda_runtime.h>
#include <cuda_fp16.h>
#include <math.h>
#include <stdint.h>

#define D_DIM 1024
#define H_DIM 2048
#define E_NUM 8
#define CAP   8192
#define N_TOK 8192
#define BM 128
#define BN 256
#define BK 64                            // halves per slab = 128 B rows

#define A_BYTES 16384                    // 128 rows x 128B
#define B_BYTES 32768                    // 256 rows x 128B
#define STAGE_BYTES (A_BYTES + B_BYTES)  // 49152
#define NSTAGE 4
#define SMEM_TOTAL (1024 + NSTAGE * STAGE_BYTES)  // 197632

// ---------------- device scratch ----------------
__device__ int    g_cnt[E_NUM];
__device__ int    g_off[E_NUM];
__device__ int    g_tok[E_NUM * CAP];
__device__ float  g_gate[E_NUM * CAP];
__device__ int    g_inv[N_TOK * 2];
__device__ float  g_imp[E_NUM];
__device__ float  g_ent;
__device__ __half g_xh[(size_t)N_TOK * D_DIM];            // x as half, k-permuted
__device__ __half g_hh[(size_t)N_TOK * 2 * H_DIM];        // h as half, k-permuted
__device__ __half g_yh[(size_t)N_TOK * 2 * D_DIM];        // gate*y as half
__device__ __half g_w1h[(size_t)E_NUM * H_DIM * D_DIM];   // [e][n=H][k'=D]
__device__ __half g_w2h[(size_t)E_NUM * D_DIM * H_DIM];   // [e][n=D][k'=H]

// k-group permutation: storage slot s holds source k = KORD[s]
__device__ __constant__ int KORD[16] = {0,1,8,9,2,3,10,11,4,5,12,13,6,7,14,15};
__device__ __forceinline__ int kslot(int r) {      // r = k & 15, even
    return (((r >> 1) & 3) << 2) + ((r >> 3) << 1);
}

// ---------------- helpers ----------------
__device__ __forceinline__ uint32_t smem_u32(const void* p) {
    uint32_t a;
    asm("{ .reg .u64 t; cvta.to.shared.u64 t, %1; cvt.u32.u64 %0, t; }" : "=r"(a) : "l"(p));
    return a;
}
#define CP16(dst, src) \
    asm volatile("cp.async.cg.shared.global [%0], [%1], 16;" :: "r"(dst), "l"(src))
#define CP_COMMIT()  asm volatile("cp.async.commit_group;" ::: "memory")
#define CP_WAIT(n)   asm volatile("cp.async.wait_group %0;" :: "n"(n) : "memory")

__device__ __forceinline__ void mma_f16(float* c, unsigned a0, unsigned a1,
                                        unsigned a2, unsigned a3,
                                        unsigned b0, unsigned b1) {
    asm volatile(
        "mma.sync.aligned.m16n8k16.row.col.f32.f16.f16.f32 "
        "{%0,%1,%2,%3}, {%4,%5,%6,%7}, {%8,%9}, {%0,%1,%2,%3};\n"
        : "+f"(c[0]), "+f"(c[1]), "+f"(c[2]), "+f"(c[3])
        : "r"(a0), "r"(a1), "r"(a2), "r"(a3), "r"(b0), "r"(b1));
}
__device__ __forceinline__ float gelu_exact(float v) {
    return 0.5f * v * (1.0f + erff(v * 0.70710678118654752440f));
}

// ---------------- shared bodies ----------------
// W[e][k][n] fp32 -> WT[e][n][k'] half, one 64x64 tile.
__device__ __forceinline__ void wtrans_body(const float* __restrict__ W,
                                            __half* __restrict__ WT,
                                            int K, int N, int nbi, int kbi, int e,
                                            float (*t)[68]) {
    int n0 = nbi * 64, k0 = kbi * 64;
    const float* Ws = W + (size_t)e * K * N + (size_t)k0 * N + n0;
    __half* Wd = WT + (size_t)e * N * K;
#pragma unroll
    for (int i = 0; i < 4; i++) {
        int idx = threadIdx.x + 256 * i;     // 0..1023
        int kr = idx >> 4, c4 = idx & 15;
        float4 v = *reinterpret_cast<const float4*>(Ws + (size_t)kr * N + c4 * 4);
        int cs = (c4 * 4) ^ (((kr >> 4) & 3) << 3);   // 8-multiple XOR: float4-safe
        *reinterpret_cast<float4*>(&t[kr][cs]) = v;
    }
    __syncthreads();
    int n = threadIdx.x >> 2, kg = (threadIdx.x & 3) * 16;
    __half hh[16];
#pragma unroll
    for (int s = 0; s < 16; s++) {
        int row = kg + KORD[s];
        hh[s] = __float2half(t[row][n ^ (((row >> 4) & 3) << 3)]);
    }
    __half* drow = Wd + (size_t)(n0 + n) * K + k0 + kg;
    *reinterpret_cast<uint4*>(drow)     = *reinterpret_cast<uint4*>(hh);
    *reinterpret_cast<uint4*>(drow + 8) = *reinterpret_cast<uint4*>(hh + 8);
}

// ---------------- prelude: router (+x->half) | W1 transpose ----------------
__global__ void prelude_k(const float* __restrict__ x,
                          const float* __restrict__ gW,
                          const float* __restrict__ gb,
                          const float* __restrict__ W1) {
    __shared__ __align__(16) char smbuf[32768];
    __shared__ float sAux[8][9];         // per-warp p[0..7] + ent

    if (blockIdx.x >= 1024) {
        int lin = blockIdx.x - 1024;     // W1: N=H_DIM (32 tiles), K=D_DIM (16 tiles)
        wtrans_body(W1, g_w1h, D_DIM, H_DIM,
                    lin & 31, (lin >> 5) & 15, lin >> 9,
                    reinterpret_cast<float(*)[68]>(smbuf));
        return;
    }

    float4* sgW = reinterpret_cast<float4*>(smbuf);   // 32 KB, 16B-swizzled
    int tid = threadIdx.x;
    for (int s = tid; s < 2048; s += 256)
        sgW[s ^ ((s >> 3) & 7)] = reinterpret_cast<const float4*>(gW)[s];
    __syncthreads();

    int wrp = tid >> 5;
    int token = blockIdx.x * 8 + wrp;
    int lane  = tid & 31;
    const float* xr = x + (size_t)token * D_DIM;
    __half* xh = g_xh + (size_t)token * D_DIM;

    float acc[8] = {0.f,0.f,0.f,0.f,0.f,0.f,0.f,0.f};
#pragma unroll
    for (int i = 0; i < 8; i++) {
        int d = lane * 4 + 128 * i;
        float4 xv = *reinterpret_cast<const float4*>(xr + d);
        int base = d & ~15, r = d & 15;
        *reinterpret_cast<__half2*>(xh + base + kslot(r)) =
            __floats2half2_rn(xv.x, xv.y);
        *reinterpret_cast<__half2*>(xh + base + kslot(r + 2)) =
            __floats2half2_rn(xv.z, xv.w);
        float xs[4] = {xv.x, xv.y, xv.z, xv.w};
#pragma unroll
        for (int q = 0; q < 4; q++) {
            int s0 = (d + q) * 2;
            float4 wa = sgW[s0 ^ ((s0 >> 3) & 7)];
            int s1 = s0 + 1;
            float4 wb = sgW[s1 ^ ((s1 >> 3) & 7)];
            acc[0] += xs[q] * wa.x; acc[1] += xs[q] * wa.y;
            acc[2] += xs[q] * wa.z; acc[3] += xs[q] * wa.w;
            acc[4] += xs[q] * wb.x; acc[5] += xs[q] * wb.y;
            acc[6] += xs[q] * wb.z; acc[7] += xs[q] * wb.w;
        }
    }
#pragma unroll
    for (int e = 0; e < 8; e++)
#pragma unroll
        for (int o = 16; o; o >>= 1) acc[e] += __shfl_xor_sync(0xffffffffu, acc[e], o);

    if (lane == 0) {
        float lg[8];
#pragma unroll
        for (int e = 0; e < 8; e++) lg[e] = acc[e] + gb[e];
        float mx = lg[0];
#pragma unroll
        for (int e = 1; e < 8; e++) mx = fmaxf(mx, lg[e]);
        float p[8], Z = 0.f;
#pragma unroll
        for (int e = 0; e < 8; e++) { p[e] = expf(lg[e] - mx); Z += p[e]; }
        float ent = 0.f;
#pragma unroll
        for (int e = 0; e < 8; e++) {
            p[e] /= Z;
            ent -= p[e] * logf(p[e] + 1e-8f);
            sAux[wrp][e] = p[e];
        }
        sAux[wrp][8] = ent;

        int e0 = 0;
#pragma unroll
        for (int e = 1; e < 8; e++) if (lg[e] > lg[e0]) e0 = e;
        int e1 = -1;
#pragma unroll
        for (int e = 0; e < 8; e++) if (e != e0 && (e1 < 0 || lg[e] > lg[e1])) e1 = e;

        float dlt = expf(lg[e1] - lg[e0]);
        float g0 = 1.0f / (1.0f + dlt);
        float g1 = dlt / (1.0f + dlt);

        int s0 = atomicAdd(&g_cnt[e0], 1);
        g_tok[e0 * CAP + s0] = token; g_gate[e0 * CAP + s0] = g0;
        int s1 = atomicAdd(&g_cnt[e1], 1);
        g_tok[e1 * CAP + s1] = token; g_gate[e1 * CAP + s1] = g1;
        g_inv[token * 2 + 0] = e0 * CAP + s0;
        g_inv[token * 2 + 1] = e1 * CAP + s1;
    }
    __syncthreads();
    // one aux atomic set per block (8x fewer global atomics)
    if (tid < 9) {
        float v = 0.f;
#pragma unroll
        for (int w = 0; w < 8; w++) v += sAux[w][tid];
        if (tid < 8) atomicAdd(&g_imp[tid], v);
        else         atomicAdd(&g_ent, v);
    }
}

// ---------------- fp16 pipelined grouped GEMM (128x256, warp 64x64, BK=64) ----------------
// MODE 0: A = gather(g_xh) [K=1024], B=g_w1h, bias+gelu -> g_hh (half, permuted)
//         blocks with blockIdx.y >= 64 instead transpose W2 -> g_w2h;
//         the lin==0 transpose block also computes g_off + the 19 tail outputs
// MODE 1: A = g_hh [K=2048], B=g_w2h, gate*(bias+c) -> g_yh (half)
template <int MODE>
__global__ void __launch_bounds__(256, 1)
gemm_h(const float* __restrict__ bias, const float* __restrict__ W2,
       float* __restrict__ out_tail) {
    constexpr int Kdim  = (MODE == 0) ? D_DIM : H_DIM;
    constexpr int Ncols = (MODE == 0) ? H_DIM : D_DIM;
    constexpr int NS    = Kdim / BK;

    extern __shared__ char smem[];

    if (MODE == 0 && blockIdx.y >= 64) {
        // W2 transpose: N=D_DIM (16 tiles), K=H_DIM (32 tiles)
        int lin = blockIdx.x + 8 * (blockIdx.y - 64) + 512 * blockIdx.z;
        wtrans_body(W2, g_w2h, H_DIM, D_DIM,
                    lin & 15, (lin >> 4) & 31, lin >> 9,
                    reinterpret_cast<float(*)[68]>(smem));
        // fold the former tail_k into one block (counters final after prelude;
        // g_off is read only by gemm_h<1>/ln_k, which launch after this kernel)
        if (lin == 0 && threadIdx.x == 0) {
            int off = 0;
            float loadv[8], impv[8];
            for (int e = 0; e < 8; e++) { g_off[e] = off; off += g_cnt[e]; }
            for (int e = 0; e < 8; e++) {
                loadv[e] = (float)g_cnt[e] / (float)N_TOK;
                impv[e]  = g_imp[e] / (float)N_TOK;
            }
            float bal = 0.f, util = 0.f;
            for (int e = 0; e < 8; e++) bal += impv[e] * loadv[e];
            bal *= (float)E_NUM;
            for (int e = 0; e < 8; e++) util -= loadv[e] * logf(loadv[e] + 1e-8f);
            out_tail[0] = bal;
            out_tail[1] = g_ent / (float)N_TOK;
            out_tail[2] = util;
            for (int e = 0; e < 8; e++) out_tail[3 + e]  = loadv[e];
            for (int e = 0; e < 8; e++) out_tail[11 + e] = impv[e];
        }
        return;
    }

    const int e = blockIdx.z;
    const int cnt = g_cnt[e];
    const int m_base = blockIdx.y * BM;
    if (m_base >= cnt) return;
    const int n_base = blockIdx.x * BN;
    // hoff: MODE 0 computes the prefix locally (g_off not yet written);
    // MODE 1 reads g_off (written during the MODE-0 kernel).
    int hoff;
    if (MODE == 0) {
        hoff = 0;
        for (int i = 0; i < e; i++) hoff += g_cnt[i];
    } else {
        hoff = g_off[e];
    }

    const int tid = threadIdx.x, wid = tid >> 5, lane = tid & 31;
    const int g = lane >> 2, tig = lane & 3;
    const int wm = (wid & 1) * 64;
    const int wn = (wid >> 1) * 64;
    const uint32_t sb = smem_u32(smem);
    float* sBias = (float*)smem;

    sBias[tid] = bias[(size_t)e * Ncols + n_base + tid];

    // ---- cp.async assignments ----
    const int cch = tid & 7;          // 16B chunk (8 halves) within 128B row
    const int r0  = tid >> 3;         // base row 0..31
    const __half* Ab = (MODE == 0) ? (const __half*)g_xh : (const __half*)g_hh;
    const __half* Wb = (MODE == 0) ? (const __half*)g_w1h : (const __half*)g_w2h;

    const __half* aSrc[4];
#pragma unroll
    for (int i = 0; i < 4; i++) {
        int am = m_base + r0 + 32 * i;
        if (am >= cnt) am = cnt - 1;
        size_t row = (MODE == 0) ? (size_t)g_tok[e * CAP + am] : (size_t)(hoff + am);
        aSrc[i] = Ab + row * Kdim + cch * 8;
    }
    const __half* bSrc = Wb + ((size_t)e * Ncols + n_base + r0) * Kdim + cch * 8;

    const uint32_t swz = (uint32_t)((cch ^ (r0 & 7)) << 4);
    const uint32_t aDst = sb + 1024 + r0 * 128 + swz;
    const uint32_t bDst = sb + 1024 + A_BYTES + r0 * 128 + swz;

    float c[4][8][4];
#pragma unroll
    for (int i = 0; i < 4; i++)
#pragma unroll
        for (int j = 0; j < 8; j++)
#pragma unroll
            for (int r = 0; r < 4; r++) c[i][j][r] = 0.f;

    auto issue = [&](int s) {
        if (s < NS) {
            const int kb = s * BK;
            const uint32_t so = (uint32_t)((s & (NSTAGE - 1)) * STAGE_BYTES);
#pragma unroll
            for (int i = 0; i < 4; i++)
                CP16(aDst + so + i * 4096, aSrc[i] + kb);
#pragma unroll
            for (int i = 0; i < 8; i++)
                CP16(bDst + so + i * 4096, bSrc + (size_t)(32 * i) * Kdim + kb);
        }
        CP_COMMIT();
    };

    issue(0); issue(1); issue(2);

    const int aRow = (wm + g) * 128;
    const int bRow = A_BYTES + (wn + g) * 128;

    for (int s = 0; s < NS; s++) {
        CP_WAIT(2);
        __syncthreads();
        issue(s + 3);

        const char* stg = smem + 1024 + (s & (NSTAGE - 1)) * STAGE_BYTES;
#pragma unroll
        for (int kx = 0; kx < 4; kx++) {
            const int off = (((2 * kx + (tig >> 1)) ^ g) << 4) + 8 * (tig & 1);
            uint2 ua0[4], ua1[4], ub[8];
#pragma unroll
            for (int i = 0; i < 4; i++) {
                ua0[i] = *(const uint2*)(stg + aRow + i * 2048 + off);
                ua1[i] = *(const uint2*)(stg + aRow + i * 2048 + 1024 + off);
            }
#pragma unroll
            for (int j = 0; j < 8; j++)
                ub[j] = *(const uint2*)(stg + bRow + j * 1024 + off);
#pragma unroll
            for (int i = 0; i < 4; i++)
#pragma unroll
                for (int j = 0; j < 8; j++)
                    mma_f16(c[i][j], ua0[i].x, ua1[i].x, ua0[i].y, ua1[i].y,
                            ub[j].x, ub[j].y);
        }
    }

    // ---- epilogue ----
#pragma unroll
    for (int i = 0; i < 4; i++) {
#pragma unroll
        for (int half = 0; half < 2; half++) {
            int mrow = m_base + wm + 16 * i + g + half * 8;
            if (mrow >= cnt) continue;
            if (MODE == 0) {
                __half* hp = g_hh + (size_t)(hoff + mrow) * H_DIM + n_base;
#pragma unroll
                for (int j = 0; j < 8; j++) {
                    int col = wn + j * 8 + tig * 2;
                    float v0 = c[i][j][half * 2 + 0] + sBias[col];
                    float v1 = c[i][j][half * 2 + 1] + sBias[col + 1];
                    int col2 = (col & ~15) + kslot(col & 15);   // permuted store
                    *reinterpret_cast<__half2*>(hp + col2) =
                        __floats2half2_rn(gelu_exact(v0), gelu_exact(v1));
                }
            } else {
                float gate = g_gate[e * CAP + mrow];
                __half* yp = g_yh + (size_t)(hoff + mrow) * D_DIM + n_base;
#pragma unroll
                for (int j = 0; j < 8; j++) {
                    int col = wn + j * 8 + tig * 2;
                    float v0 = gate * (c[i][j][half * 2 + 0] + sBias[col]);
                    float v1 = gate * (c[i][j][half * 2 + 1] + sBias[col + 1]);
                    *reinterpret_cast<__half2*>(yp + col) = __floats2half2_rn(v0, v1);
                }
            }
        }
    }
}

// ---------------- LayerNorm: 4 tokens/block, 64-thread groups ----------------
__global__ void ln_k(const float* __restrict__ x,
                     const float* __restrict__ gamma,
                     const float* __restrict__ beta,
                     float* __restrict__ out) {
    __shared__ float ws[4][2], wq[4][2];
    int tid = threadIdx.x;
    int grp = tid >> 6, gtid = tid & 63;
    int glane = gtid & 31, gwarp = gtid >> 5;
    int token = blockIdx.x * 4 + grp;

    // counters no longer read this launch; re-zero for next graph replay
    if (blockIdx.x == 0 && tid < 9) {
        if (tid < 8) { g_cnt[tid] = 0; g_imp[tid] = 0.0f; }
        else         g_ent = 0.0f;
    }

    int i0 = g_inv[token * 2 + 0], i1 = g_inv[token * 2 + 1];
    size_t r0 = (size_t)(g_off[i0 >> 13] + (i0 & (CAP - 1)));
    size_t r1 = (size_t)(g_off[i1 >> 13] + (i1 & (CAP - 1)));
    const __half* y0 = g_yh + r0 * D_DIM;
    const __half* y1 = g_yh + r1 * D_DIM;
    const float* xr = x + (size_t)token * D_DIM;

    const int c = gtid * 16;
    float4 xv[4];
#pragma unroll
    for (int v = 0; v < 4; v++)
        xv[v] = *reinterpret_cast<const float4*>(xr + c + v * 4);
    uint4 ya0 = *reinterpret_cast<const uint4*>(y0 + c);
    uint4 ya1 = *reinterpret_cast<const uint4*>(y0 + c + 8);
    uint4 yb0 = *reinterpret_cast<const uint4*>(y1 + c);
    uint4 yb1 = *reinterpret_cast<const uint4*>(y1 + c + 8);

    float z[16];
    {
        const __half2* ha = reinterpret_cast<const __half2*>(&ya0);
        const __half2* hb = reinterpret_cast<const __half2*>(&yb0);
        const float* xf = reinterpret_cast<const float*>(xv);
#pragma unroll
        for (int k = 0; k < 4; k++) {
            float2 fa = __half22float2(ha[k]);
            float2 fb = __half22float2(hb[k]);
            z[2 * k + 0] = xf[2 * k + 0] + fa.x + fb.x;
            z[2 * k + 1] = xf[2 * k + 1] + fa.y + fb.y;
        }
        const __half2* ha1 = reinterpret_cast<const __half2*>(&ya1);
        const __half2* hb1 = reinterpret_cast<const __half2*>(&yb1);
#pragma unroll
        for (int k = 0; k < 4; k++) {
            float2 fa = __half22float2(ha1[k]);
            float2 fb = __half22float2(hb1[k]);
            z[8 + 2 * k + 0] = xf[8 + 2 * k + 0] + fa.x + fb.x;
            z[8 + 2 * k + 1] = xf[8 + 2 * k + 1] + fa.y + fb.y;
        }
    }

    float s = 0.f, sq = 0.f;
#pragma unroll
    for (int k = 0; k < 16; k++) { s += z[k]; sq += z[k] * z[k]; }
#pragma unroll
    for (int o = 16; o; o >>= 1) {
        s  += __shfl_xor_sync(0xffffffffu, s, o);
        sq += __shfl_xor_sync(0xffffffffu, sq, o);
    }
    if (glane == 0) { ws[grp][gwarp] = s; wq[grp][gwarp] = sq; }
    __syncthreads();
    float st = ws[grp][0] + ws[grp][1];
    float qt = wq[grp][0] + wq[grp][1];
    float mu  = st * (1.0f / D_DIM);
    float var = qt * (1.0f / D_DIM) - mu * mu;
    float inv = rsqrtf(var + 1e-5f);

    float* op = out + (size_t)token * D_DIM + c;
#pragma unroll
    for (int v = 0; v < 4; v++) {
        float4 gm = *reinterpret_cast<const float4*>(gamma + c + v * 4);
        float4 bt = *reinterpret_cast<const float4*>(beta + c + v * 4);
        float4 o;
        o.x = (z[v * 4 + 0] - mu) * inv * gm.x + bt.x;
        o.y = (z[v * 4 + 1] - mu) * inv * gm.y + bt.y;
        o.z = (z[v * 4 + 2] - mu) * inv * gm.z + bt.z;
        o.w = (z[v * 4 + 3] - mu) * inv * gm.w + bt.w;
        *reinterpret_cast<float4*>(op + v * 4) = o;
    }
}

// ---------------- launch ----------------
extern "C" void kernel_launch(void* const* d_in, const int* in_sizes, int n_in,
                              void* d_out, int out_size) {
    (void)in_sizes; (void)n_in; (void)out_size;
    const float* x     = (const float*)d_in[0];
    const float* gW    = (const float*)d_in[1];
    const float* gb    = (const float*)d_in[2];
    const float* W1    = (const float*)d_in[3];
    const float* b1    = (const float*)d_in[4];
    const float* W2    = (const float*)d_in[5];
    const float* b2    = (const float*)d_in[6];
    const float* gamma = (const float*)d_in[7];
    const float* beta  = (const float*)d_in[8];
    float* out = (float*)d_out;
    float* out_tail = out + (size_t)N_TOK * D_DIM;

    cudaFuncSetAttribute((const void*)gemm_h<0>,
                         cudaFuncAttributeMaxDynamicSharedMemorySize, SMEM_TOTAL);
    cudaFuncSetAttribute((const void*)gemm_h<1>,
                         cudaFuncAttributeMaxDynamicSharedMemorySize, SMEM_TOTAL);

    prelude_k<<<1024 + 4096, 256>>>(x, gW, gb, W1);      // router + W1 transpose
    // GEMM1 (by<64) + W2 transpose (by>=64) + tail outputs (lin==0 block)
    gemm_h<0><<<dim3(H_DIM / BN, 128, E_NUM), 256, SMEM_TOTAL>>>(b1, W2, out_tail);
    gemm_h<1><<<dim3(D_DIM / BN, CAP / BM, E_NUM), 256, SMEM_TOTAL>>>(b2, nullptr, nullptr);
    ln_k<<<N_TOK / 4, 256>>>(x, gamma, beta, out);       // + counter reset for next replay
}

// round 16
// speedup vs baseline: 1.2715x; 1.0124x over previous
#include <cuda_runtime.h>
#include <cuda_fp16.h>
#include <math.h>
#include <stdint.h>

#define D_DIM 1024
#define H_DIM 2048
#define E_NUM 8
#define CAP   8192
#define N_TOK 8192
#define BM 128
#define BN 256
#define BK 64                            // halves per slab = 128 B rows

#define A_BYTES 16384                    // 128 rows x 128B
#define B_BYTES 32768                    // 256 rows x 128B
#define STAGE_BYTES (A_BYTES + B_BYTES)  // 49152
#define NSTAGE 4
#define SMEM_TOTAL (1024 + NSTAGE * STAGE_BYTES)  // 197632

// ---------------- device scratch ----------------
__device__ int    g_cnt[E_NUM];
__device__ int    g_off[E_NUM];
__device__ int    g_tok[E_NUM * CAP];
__device__ float  g_gate[E_NUM * CAP];
__device__ int    g_inv[N_TOK * 2];
__device__ float  g_imp[E_NUM];
__device__ float  g_ent;
__device__ __half g_xh[(size_t)N_TOK * D_DIM];            // x as half, k-permuted
__device__ __half g_hh[(size_t)N_TOK * 2 * H_DIM];        // h as half, k-permuted
__device__ __half g_yh[(size_t)N_TOK * 2 * D_DIM];        // gate*y as half
__device__ __half g_w1h[(size_t)E_NUM * H_DIM * D_DIM];   // [e][n=H][k'=D]
__device__ __half g_w2h[(size_t)E_NUM * D_DIM * H_DIM];   // [e][n=D][k'=H]

// k-group permutation: storage slot s holds source k = KORD[s]
__device__ __constant__ int KORD[16] = {0,1,8,9,2,3,10,11,4,5,12,13,6,7,14,15};
__device__ __forceinline__ int kslot(int r) {      // r = k & 15, even
    return (((r >> 1) & 3) << 2) + ((r >> 3) << 1);
}

// ---------------- helpers ----------------
__device__ __forceinline__ uint32_t smem_u32(const void* p) {
    uint32_t a;
    asm("{ .reg .u64 t; cvta.to.shared.u64 t, %1; cvt.u32.u64 %0, t; }" : "=r"(a) : "l"(p));
    return a;
}
#define CP16(dst, src) \
    asm volatile("cp.async.cg.shared.global [%0], [%1], 16;" :: "r"(dst), "l"(src))
#define CP_COMMIT()  asm volatile("cp.async.commit_group;" ::: "memory")
#define CP_WAIT(n)   asm volatile("cp.async.wait_group %0;" :: "n"(n) : "memory")

__device__ __forceinline__ void mma_f16(float* c, unsigned a0, unsigned a1,
                                        unsigned a2, unsigned a3,
                                        unsigned b0, unsigned b1) {
    asm volatile(
        "mma.sync.aligned.m16n8k16.row.col.f32.f16.f16.f32 "
        "{%0,%1,%2,%3}, {%4,%5,%6,%7}, {%8,%9}, {%0,%1,%2,%3};\n"
        : "+f"(c[0]), "+f"(c[1]), "+f"(c[2]), "+f"(c[3])
        : "r"(a0), "r"(a1), "r"(a2), "r"(a3), "r"(b0), "r"(b1));
}
__device__ __forceinline__ float gelu_exact(float v) {
    return 0.5f * v * (1.0f + erff(v * 0.70710678118654752440f));
}

// ---------------- shared bodies ----------------
// W[e][k][n] fp32 -> WT[e][n][k'] half, one 64x64 tile.
__device__ __forceinline__ void wtrans_body(const float* __restrict__ W,
                                            __half* __restrict__ WT,
                                            int K, int N, int nbi, int kbi, int e,
                                            float (*t)[68]) {
    int n0 = nbi * 64, k0 = kbi * 64;
    const float* Ws = W + (size_t)e * K * N + (size_t)k0 * N + n0;
    __half* Wd = WT + (size_t)e * N * K;
#pragma unroll
    for (int i = 0; i < 4; i++) {
        int idx = threadIdx.x + 256 * i;     // 0..1023
        int kr = idx >> 4, c4 = idx & 15;
        float4 v = *reinterpret_cast<const float4*>(Ws + (size_t)kr * N + c4 * 4);
        int cs = (c4 * 4) ^ (((kr >> 4) & 3) << 3);   // 8-multiple XOR: float4-safe
        *reinterpret_cast<float4*>(&t[kr][cs]) = v;
    }
    __syncthreads();
    int n = threadIdx.x >> 2, kg = (threadIdx.x & 3) * 16;
    __half hh[16];
#pragma unroll
    for (int s = 0; s < 16; s++) {
        int row = kg + KORD[s];
        hh[s] = __float2half(t[row][n ^ (((row >> 4) & 3) << 3)]);
    }
    __half* drow = Wd + (size_t)(n0 + n) * K + k0 + kg;
    *reinterpret_cast<uint4*>(drow)     = *reinterpret_cast<uint4*>(hh);
    *reinterpret_cast<uint4*>(drow + 8) = *reinterpret_cast<uint4*>(hh + 8);
}

// ---------------- prelude: router (+x->half) | W1 transpose ----------------
__global__ void prelude_k(const float* __restrict__ x,
                          const float* __restrict__ gW,
                          const float* __restrict__ gb,
                          const float* __restrict__ W1) {
    __shared__ __align__(16) char smbuf[32768];
    __shared__ float sAux[8][9];         // per-warp p[0..7] + ent

    if (blockIdx.x >= 1024) {
        int lin = blockIdx.x - 1024;     // W1: N=H_DIM (32 tiles), K=D_DIM (16 tiles)
        wtrans_body(W1, g_w1h, D_DIM, H_DIM,
                    lin & 31, (lin >> 5) & 15, lin >> 9,
                    reinterpret_cast<float(*)[68]>(smbuf));
        return;
    }

    float4* sgW = reinterpret_cast<float4*>(smbuf);   // 32 KB, 16B-swizzled
    int tid = threadIdx.x;
    for (int s = tid; s < 2048; s += 256)
        sgW[s ^ ((s >> 3) & 7)] = reinterpret_cast<const float4*>(gW)[s];
    __syncthreads();

    int wrp = tid >> 5;
    int token = blockIdx.x * 8 + wrp;
    int lane  = tid & 31;
    const float* xr = x + (size_t)token * D_DIM;
    __half* xh = g_xh + (size_t)token * D_DIM;

    float acc[8] = {0.f,0.f,0.f,0.f,0.f,0.f,0.f,0.f};
#pragma unroll
    for (int i = 0; i < 8; i++) {
        int d = lane * 4 + 128 * i;
        float4 xv = *reinterpret_cast<const float4*>(xr + d);
        int base = d & ~15, r = d & 15;
        *reinterpret_cast<__half2*>(xh + base + kslot(r)) =
            __floats2half2_rn(xv.x, xv.y);
        *reinterpret_cast<__half2*>(xh + base + kslot(r + 2)) =
            __floats2half2_rn(xv.z, xv.w);
        float xs[4] = {xv.x, xv.y, xv.z, xv.w};
#pragma unroll
        for (int q = 0; q < 4; q++) {
            int s0 = (d + q) * 2;
            float4 wa = sgW[s0 ^ ((s0 >> 3) & 7)];
            int s1 = s0 + 1;
            float4 wb = sgW[s1 ^ ((s1 >> 3) & 7)];
            acc[0] += xs[q] * wa.x; acc[1] += xs[q] * wa.y;
            acc[2] += xs[q] * wa.z; acc[3] += xs[q] * wa.w;
            acc[4] += xs[q] * wb.x; acc[5] += xs[q] * wb.y;
            acc[6] += xs[q] * wb.z; acc[7] += xs[q] * wb.w;
        }
    }
#pragma unroll
    for (int e = 0; e < 8; e++)
#pragma unroll
        for (int o = 16; o; o >>= 1) acc[e] += __shfl_xor_sync(0xffffffffu, acc[e], o);

    if (lane == 0) {
        float lg[8];
#pragma unroll
        for (int e = 0; e < 8; e++) lg[e] = acc[e] + gb[e];
        float mx = lg[0];
#pragma unroll
        for (int e = 1; e < 8; e++) mx = fmaxf(mx, lg[e]);
        float p[8], Z = 0.f;
#pragma unroll
        for (int e = 0; e < 8; e++) { p[e] = expf(lg[e] - mx); Z += p[e]; }
        float ent = 0.f;
#pragma unroll
        for (int e = 0; e < 8; e++) {
            p[e] /= Z;
            ent -= p[e] * logf(p[e] + 1e-8f);
            sAux[wrp][e] = p[e];
        }
        sAux[wrp][8] = ent;

        int e0 = 0;
#pragma unroll
        for (int e = 1; e < 8; e++) if (lg[e] > lg[e0]) e0 = e;
        int e1 = -1;
#pragma unroll
        for (int e = 0; e < 8; e++) if (e != e0 && (e1 < 0 || lg[e] > lg[e1])) e1 = e;

        float dlt = expf(lg[e1] - lg[e0]);
        float g0 = 1.0f / (1.0f + dlt);
        float g1 = dlt / (1.0f + dlt);

        int s0 = atomicAdd(&g_cnt[e0], 1);
        g_tok[e0 * CAP + s0] = token; g_gate[e0 * CAP + s0] = g0;
        int s1 = atomicAdd(&g_cnt[e1], 1);
        g_tok[e1 * CAP + s1] = token; g_gate[e1 * CAP + s1] = g1;
        g_inv[token * 2 + 0] = e0 * CAP + s0;
        g_inv[token * 2 + 1] = e1 * CAP + s1;
    }
    __syncthreads();
    // one aux atomic set per block (8x fewer global atomics)
    if (tid < 9) {
        float v = 0.f;
#pragma unroll
        for (int w = 0; w < 8; w++) v += sAux[w][tid];
        if (tid < 8) atomicAdd(&g_imp[tid], v);
        else         atomicAdd(&g_ent, v);
    }
}

// ---------------- fp16 pipelined grouped GEMM (128x256, warp 64x64, BK=64) ----------------
// MODE 0: A = gather(g_xh) [K=1024], B=g_w1h, bias+gelu -> g_hh (half, permuted)
//         blocks with blockIdx.y >= 64 instead transpose W2 -> g_w2h;
//         the lin==0 transpose block also computes g_off + the 19 tail outputs
// MODE 1: A = g_hh [K=2048], B=g_w2h, gate*(bias+c) -> g_yh (half)
template <int MODE>
__global__ void __launch_bounds__(256, 1)
gemm_h(const float* __restrict__ bias, const float* __restrict__ W2,
       float* __restrict__ out_tail) {
    constexpr int Kdim  = (MODE == 0) ? D_DIM : H_DIM;
    constexpr int Ncols = (MODE == 0) ? H_DIM : D_DIM;
    constexpr int NS    = Kdim / BK;

    extern __shared__ char smem[];

    if (MODE == 0 && blockIdx.y >= 64) {
        // W2 transpose: N=D_DIM (16 tiles), K=H_DIM (32 tiles)
        int lin = blockIdx.x + 8 * (blockIdx.y - 64) + 512 * blockIdx.z;
        wtrans_body(W2, g_w2h, H_DIM, D_DIM,
                    lin & 15, (lin >> 4) & 31, lin >> 9,
                    reinterpret_cast<float(*)[68]>(smem));
        // fold the former tail_k into one block (counters final after prelude;
        // g_off is read only by gemm_h<1>/ln_k, which launch after this kernel)
        if (lin == 0 && threadIdx.x == 0) {
            int off = 0;
            float loadv[8], impv[8];
            for (int e = 0; e < 8; e++) { g_off[e] = off; off += g_cnt[e]; }
            for (int e = 0; e < 8; e++) {
                loadv[e] = (float)g_cnt[e] / (float)N_TOK;
                impv[e]  = g_imp[e] / (float)N_TOK;
            }
            float bal = 0.f, util = 0.f;
            for (int e = 0; e < 8; e++) bal += impv[e] * loadv[e];
            bal *= (float)E_NUM;
            for (int e = 0; e < 8; e++) util -= loadv[e] * logf(loadv[e] + 1e-8f);
            out_tail[0] = bal;
            out_tail[1] = g_ent / (float)N_TOK;
            out_tail[2] = util;
            for (int e = 0; e < 8; e++) out_tail[3 + e]  = loadv[e];
            for (int e = 0; e < 8; e++) out_tail[11 + e] = impv[e];
        }
        return;
    }

    const int e = blockIdx.z;
    const int cnt = g_cnt[e];
    const int m_base = blockIdx.y * BM;
    if (m_base >= cnt) return;
    const int n_base = blockIdx.x * BN;
    // hoff: MODE 0 computes the prefix locally (g_off not yet written);
    // MODE 1 reads g_off (written during the MODE-0 kernel).
    int hoff;
    if (MODE == 0) {
        hoff = 0;
        for (int i = 0; i < e; i++) hoff += g_cnt[i];
    } else {
        hoff = g_off[e];
    }

    const int tid = threadIdx.x, wid = tid >> 5, lane = tid & 31;
    const int g = lane >> 2, tig = lane & 3;
    const int wm = (wid & 1) * 64;
    const int wn = (wid >> 1) * 64;
    const uint32_t sb = smem_u32(smem);
    float* sBias = (float*)smem;

    sBias[tid] = bias[(size_t)e * Ncols + n_base + tid];

    // ---- cp.async assignments ----
    const int cch = tid & 7;          // 16B chunk (8 halves) within 128B row
    const int r0  = tid >> 3;         // base row 0..31
    const __half* Ab = (MODE == 0) ? (const __half*)g_xh : (const __half*)g_hh;
    const __half* Wb = (MODE == 0) ? (const __half*)g_w1h : (const __half*)g_w2h;

    const __half* aSrc[4];
#pragma unroll
    for (int i = 0; i < 4; i++) {
        int am = m_base + r0 + 32 * i;
        if (am >= cnt) am = cnt - 1;
        size_t row = (MODE == 0) ? (size_t)g_tok[e * CAP + am] : (size_t)(hoff + am);
        aSrc[i] = Ab + row * Kdim + cch * 8;
    }
    const __half* bSrc = Wb + ((size_t)e * Ncols + n_base + r0) * Kdim + cch * 8;

    const uint32_t swz = (uint32_t)((cch ^ (r0 & 7)) << 4);
    const uint32_t aDst = sb + 1024 + r0 * 128 + swz;
    const uint32_t bDst = sb + 1024 + A_BYTES + r0 * 128 + swz;

    float c[4][8][4];
#pragma unroll
    for (int i = 0; i < 4; i++)
#pragma unroll
        for (int j = 0; j < 8; j++)
#pragma unroll
            for (int r = 0; r < 4; r++) c[i][j][r] = 0.f;

    auto issue = [&](int s) {
        if (s < NS) {
            const int kb = s * BK;
            const uint32_t so = (uint32_t)((s & (NSTAGE - 1)) * STAGE_BYTES);
#pragma unroll
            for (int i = 0; i < 4; i++)
                CP16(aDst + so + i * 4096, aSrc[i] + kb);
#pragma unroll
            for (int i = 0; i < 8; i++)
                CP16(bDst + so + i * 4096, bSrc + (size_t)(32 * i) * Kdim + kb);
        }
        CP_COMMIT();
    };

    issue(0); issue(1); issue(2);

    const int aRow = (wm + g) * 128;
    const int bRow = A_BYTES + (wn + g) * 128;

    for (int s = 0; s < NS; s++) {
        CP_WAIT(2);
        __syncthreads();
        issue(s + 3);

        const char* stg = smem + 1024 + (s & (NSTAGE - 1)) * STAGE_BYTES;
#pragma unroll
        for (int kx = 0; kx < 4; kx++) {
            const int off = (((2 * kx + (tig >> 1)) ^ g) << 4) + 8 * (tig & 1);
            uint2 ua0[4], ua1[4], ub[8];
#pragma unroll
            for (int i = 0; i < 4; i++) {
                ua0[i] = *(const uint2*)(stg + aRow + i * 2048 + off);
                ua1[i] = *(const uint2*)(stg + aRow + i * 2048 + 1024 + off);
            }
#pragma unroll
            for (int j = 0; j < 8; j++)
                ub[j] = *(const uint2*)(stg + bRow + j * 1024 + off);
#pragma unroll
            for (int i = 0; i < 4; i++)
#pragma unroll
                for (int j = 0; j < 8; j++)
                    mma_f16(c[i][j], ua0[i].x, ua1[i].x, ua0[i].y, ua1[i].y,
                            ub[j].x, ub[j].y);
        }
    }

    // ---- epilogue ----
#pragma unroll
    for (int i = 0; i < 4; i++) {
#pragma unroll
        for (int half = 0; half < 2; half++) {
            int mrow = m_base + wm + 16 * i + g + half * 8;
            if (mrow >= cnt) continue;
            if (MODE == 0) {
                __half* hp = g_hh + (size_t)(hoff + mrow) * H_DIM + n_base;
#pragma unroll
                for (int j = 0; j < 8; j++) {
                    int col = wn + j * 8 + tig * 2;
                    float v0 = c[i][j][half * 2 + 0] + sBias[col];
                    float v1 = c[i][j][half * 2 + 1] + sBias[col + 1];
                    int col2 = (col & ~15) + kslot(col & 15);   // permuted store
                    *reinterpret_cast<__half2*>(hp + col2) =
                        __floats2half2_rn(gelu_exact(v0), gelu_exact(v1));
                }
            } else {
                float gate = g_gate[e * CAP + mrow];
                __half* yp = g_yh + (size_t)(hoff + mrow) * D_DIM + n_base;
#pragma unroll
                for (int j = 0; j < 8; j++) {
                    int col = wn + j * 8 + tig * 2;
                    float v0 = gate * (c[i][j][half * 2 + 0] + sBias[col]);
                    float v1 = gate * (c[i][j][half * 2 + 1] + sBias[col + 1]);
                    *reinterpret_cast<__half2*>(yp + col) = __floats2half2_rn(v0, v1);
                }
            }
        }
    }
}

// ---------------- LayerNorm: 2 tokens/block, 128 threads/token, 8 floats/thread ----------------
__global__ void ln_k(const float* __restrict__ x,
                     const float* __restrict__ gamma,
                     const float* __restrict__ beta,
                     float* __restrict__ out) {
    __shared__ float ws[2][4], wq[2][4];
    int tid = threadIdx.x;
    int grp = tid >> 7, gtid = tid & 127;
    int glane = gtid & 31, gwarp = gtid >> 5;   // 4 warps per group
    int token = blockIdx.x * 2 + grp;

    // counters no longer read this launch; re-zero for next graph replay
    if (blockIdx.x == 0 && tid < 9) {
        if (tid < 8) { g_cnt[tid] = 0; g_imp[tid] = 0.0f; }
        else         g_ent = 0.0f;
    }

    int i0 = g_inv[token * 2 + 0], i1 = g_inv[token * 2 + 1];
    size_t r0 = (size_t)(g_off[i0 >> 13] + (i0 & (CAP - 1)));
    size_t r1 = (size_t)(g_off[i1 >> 13] + (i1 & (CAP - 1)));
    const __half* y0 = g_yh + r0 * D_DIM;
    const __half* y1 = g_yh + r1 * D_DIM;
    const float* xr = x + (size_t)token * D_DIM;

    const int c = gtid * 8;
    float4 xv0 = *reinterpret_cast<const float4*>(xr + c);
    float4 xv1 = *reinterpret_cast<const float4*>(xr + c + 4);
    uint4 ya = *reinterpret_cast<const uint4*>(y0 + c);   // 8 halves
    uint4 yb = *reinterpret_cast<const uint4*>(y1 + c);

    float z[8];
    {
        const __half2* ha = reinterpret_cast<const __half2*>(&ya);
        const __half2* hb = reinterpret_cast<const __half2*>(&yb);
        float xf[8] = {xv0.x, xv0.y, xv0.z, xv0.w, xv1.x, xv1.y, xv1.z, xv1.w};
#pragma unroll
        for (int k = 0; k < 4; k++) {
            float2 fa = __half22float2(ha[k]);
            float2 fb = __half22float2(hb[k]);
            z[2 * k + 0] = xf[2 * k + 0] + fa.x + fb.x;
            z[2 * k + 1] = xf[2 * k + 1] + fa.y + fb.y;
        }
    }

    float s = 0.f, sq = 0.f;
#pragma unroll
    for (int k = 0; k < 8; k++) { s += z[k]; sq += z[k] * z[k]; }
#pragma unroll
    for (int o = 16; o; o >>= 1) {
        s  += __shfl_xor_sync(0xffffffffu, s, o);
        sq += __shfl_xor_sync(0xffffffffu, sq, o);
    }
    if (glane == 0) { ws[grp][gwarp] = s; wq[grp][gwarp] = sq; }
    __syncthreads();
    float st = ws[grp][0] + ws[grp][1] + ws[grp][2] + ws[grp][3];
    float qt = wq[grp][0] + wq[grp][1] + wq[grp][2] + wq[grp][3];
    float mu  = st * (1.0f / D_DIM);
    float var = qt * (1.0f / D_DIM) - mu * mu;
    float inv = rsqrtf(var + 1e-5f);

    float* op = out + (size_t)token * D_DIM + c;
#pragma unroll
    for (int v = 0; v < 2; v++) {
        float4 gm = *reinterpret_cast<const float4*>(gamma + c + v * 4);
        float4 bt = *reinterpret_cast<const float4*>(beta + c + v * 4);
        float4 o;
        o.x = (z[v * 4 + 0] - mu) * inv * gm.x + bt.x;
        o.y = (z[v * 4 + 1] - mu) * inv * gm.y + bt.y;
        o.z = (z[v * 4 + 2] - mu) * inv * gm.z + bt.z;
        o.w = (z[v * 4 + 3] - mu) * inv * gm.w + bt.w;
        *reinterpret_cast<float4*>(op + v * 4) = o;
    }
}

// ---------------- launch ----------------
extern "C" void kernel_launch(void* const* d_in, const int* in_sizes, int n_in,
                              void* d_out, int out_size) {
    (void)in_sizes; (void)n_in; (void)out_size;
    const float* x     = (const float*)d_in[0];
    const float* gW    = (const float*)d_in[1];
    const float* gb    = (const float*)d_in[2];
    const float* W1    = (const float*)d_in[3];
    const float* b1    = (const float*)d_in[4];
    const float* W2    = (const float*)d_in[5];
    const float* b2    = (const float*)d_in[6];
    const float* gamma = (const float*)d_in[7];
    const float* beta  = (const float*)d_in[8];
    float* out = (float*)d_out;
    float* out_tail = out + (size_t)N_TOK * D_DIM;

    cudaFuncSetAttribute((const void*)gemm_h<0>,
                         cudaFuncAttributeMaxDynamicSharedMemorySize, SMEM_TOTAL);
    cudaFuncSetAttribute((const void*)gemm_h<1>,
                         cudaFuncAttributeMaxDynamicSharedMemorySize, SMEM_TOTAL);

    prelude_k<<<1024 + 4096, 256>>>(x, gW, gb, W1);      // router + W1 transpose
    // GEMM1 (by<64) + W2 transpose (by>=64) + tail outputs (lin==0 block)
    gemm_h<0><<<dim3(H_DIM / BN, 128, E_NUM), 256, SMEM_TOTAL>>>(b1, W2, out_tail);
    gemm_h<1><<<dim3(D_DIM / BN, CAP / BM, E_NUM), 256, SMEM_TOTAL>>>(b2, nullptr, nullptr);
    ln_k<<<N_TOK / 2, 256>>>(x, gamma, beta, out);       // + counter reset for next replay
}

// round 17
// speedup vs baseline: 1.3122x; 1.0320x over previous
#include <cuda_runtime.h>
#include <cuda_fp16.h>
#include <math.h>
#include <stdint.h>

#define D_DIM 1024
#define H_DIM 2048
#define E_NUM 8
#define CAP   8192
#define N_TOK 8192
#define BM 128
#define BN 256
#define BK 64                            // halves per slab = 128 B rows

#define A_BYTES 16384                    // 128 rows x 128B
#define B_BYTES 32768                    // 256 rows x 128B
#define STAGE_BYTES (A_BYTES + B_BYTES)  // 49152
#define NSTAGE 4
#define SMEM_TOTAL (1024 + NSTAGE * STAGE_BYTES)  // 197632

// ---------------- device scratch ----------------
__device__ int    g_cnt[E_NUM];
__device__ int    g_off[E_NUM];
__device__ int    g_tok[E_NUM * CAP];
__device__ float  g_gate[E_NUM * CAP];
__device__ int    g_inv[N_TOK * 2];
__device__ float  g_imp[E_NUM];
__device__ float  g_ent;
__device__ __half g_xh[(size_t)N_TOK * D_DIM];            // x as half, k-permuted
__device__ __half g_hh[(size_t)N_TOK * 2 * H_DIM];        // h as half, k-permuted
__device__ __half g_yh[(size_t)N_TOK * 2 * D_DIM];        // gate*y as half
__device__ __half g_w1h[(size_t)E_NUM * H_DIM * D_DIM];   // [e][n=H][k'=D]
__device__ __half g_w2h[(size_t)E_NUM * D_DIM * H_DIM];   // [e][n=D][k'=H]

// k-group permutation: storage slot s holds source k = KORD[s]
__device__ __constant__ int KORD[16] = {0,1,8,9,2,3,10,11,4,5,12,13,6,7,14,15};
__device__ __forceinline__ int kslot(int r) {      // r = k & 15, even
    return (((r >> 1) & 3) << 2) + ((r >> 3) << 1);
}

// ---------------- helpers ----------------
__device__ __forceinline__ uint32_t smem_u32(const void* p) {
    uint32_t a;
    asm("{ .reg .u64 t; cvta.to.shared.u64 t, %1; cvt.u32.u64 %0, t; }" : "=r"(a) : "l"(p));
    return a;
}
#define CP16(dst, src) \
    asm volatile("cp.async.cg.shared.global [%0], [%1], 16;" :: "r"(dst), "l"(src))
#define CP_COMMIT()  asm volatile("cp.async.commit_group;" ::: "memory")
#define CP_WAIT(n)   asm volatile("cp.async.wait_group %0;" :: "n"(n) : "memory")

__device__ __forceinline__ void mma_f16(float* c, unsigned a0, unsigned a1,
                                        unsigned a2, unsigned a3,
                                        unsigned b0, unsigned b1) {
    asm volatile(
        "mma.sync.aligned.m16n8k16.row.col.f32.f16.f16.f32 "
        "{%0,%1,%2,%3}, {%4,%5,%6,%7}, {%8,%9}, {%0,%1,%2,%3};\n"
        : "+f"(c[0]), "+f"(c[1]), "+f"(c[2]), "+f"(c[3])
        : "r"(a0), "r"(a1), "r"(a2), "r"(a3), "r"(b0), "r"(b1));
}
__device__ __forceinline__ float gelu_exact(float v) {
    return 0.5f * v * (1.0f + erff(v * 0.70710678118654752440f));
}

// ---------------- shared bodies ----------------
// W[e][k][n] fp32 -> WT[e][n][k'] half, one 64x64 tile.
__device__ __forceinline__ void wtrans_body(const float* __restrict__ W,
                                            __half* __restrict__ WT,
                                            int K, int N, int nbi, int kbi, int e,
                                            float (*t)[68]) {
    int n0 = nbi * 64, k0 = kbi * 64;
    const float* Ws = W + (size_t)e * K * N + (size_t)k0 * N + n0;
    __half* Wd = WT + (size_t)e * N * K;
#pragma unroll
    for (int i = 0; i < 4; i++) {
        int idx = threadIdx.x + 256 * i;     // 0..1023
        int kr = idx >> 4, c4 = idx & 15;
        float4 v = *reinterpret_cast<const float4*>(Ws + (size_t)kr * N + c4 * 4);
        int cs = (c4 * 4) ^ (((kr >> 4) & 3) << 3);   // 8-multiple XOR: float4-safe
        *reinterpret_cast<float4*>(&t[kr][cs]) = v;
    }
    __syncthreads();
    int n = threadIdx.x >> 2, kg = (threadIdx.x & 3) * 16;
    __half hh[16];
#pragma unroll
    for (int s = 0; s < 16; s++) {
        int row = kg + KORD[s];
        hh[s] = __float2half(t[row][n ^ (((row >> 4) & 3) << 3)]);
    }
    __half* drow = Wd + (size_t)(n0 + n) * K + k0 + kg;
    *reinterpret_cast<uint4*>(drow)     = *reinterpret_cast<uint4*>(hh);
    *reinterpret_cast<uint4*>(drow + 8) = *reinterpret_cast<uint4*>(hh + 8);
}

// ---------------- prelude: router (+x->half) | W1 transpose | W2 transpose ----------------
__global__ void prelude_k(const float* __restrict__ x,
                          const float* __restrict__ gW,
                          const float* __restrict__ gb,
                          const float* __restrict__ W1,
                          const float* __restrict__ W2) {
    __shared__ __align__(16) char smbuf[32768];
    __shared__ float sAux[8][9];         // per-warp p[0..7] + ent

    if (blockIdx.x >= 1024 + 4096) {
        int lin = blockIdx.x - (1024 + 4096);  // W2: N=D_DIM (16 tiles), K=H_DIM (32 tiles)
        wtrans_body(W2, g_w2h, H_DIM, D_DIM,
                    lin & 15, (lin >> 4) & 31, lin >> 9,
                    reinterpret_cast<float(*)[68]>(smbuf));
        return;
    }
    if (blockIdx.x >= 1024) {
        int lin = blockIdx.x - 1024;     // W1: N=H_DIM (32 tiles), K=D_DIM (16 tiles)
        wtrans_body(W1, g_w1h, D_DIM, H_DIM,
                    lin & 31, (lin >> 5) & 15, lin >> 9,
                    reinterpret_cast<float(*)[68]>(smbuf));
        return;
    }

    float4* sgW = reinterpret_cast<float4*>(smbuf);   // 32 KB, 16B-swizzled
    int tid = threadIdx.x;
    for (int s = tid; s < 2048; s += 256)
        sgW[s ^ ((s >> 3) & 7)] = reinterpret_cast<const float4*>(gW)[s];
    __syncthreads();

    int wrp = tid >> 5;
    int token = blockIdx.x * 8 + wrp;
    int lane  = tid & 31;
    const float* xr = x + (size_t)token * D_DIM;
    __half* xh = g_xh + (size_t)token * D_DIM;

    float acc[8] = {0.f,0.f,0.f,0.f,0.f,0.f,0.f,0.f};
#pragma unroll
    for (int i = 0; i < 8; i++) {
        int d = lane * 4 + 128 * i;
        float4 xv = *reinterpret_cast<const float4*>(xr + d);
        int base = d & ~15, r = d & 15;
        *reinterpret_cast<__half2*>(xh + base + kslot(r)) =
            __floats2half2_rn(xv.x, xv.y);
        *reinterpret_cast<__half2*>(xh + base + kslot(r + 2)) =
            __floats2half2_rn(xv.z, xv.w);
        float xs[4] = {xv.x, xv.y, xv.z, xv.w};
#pragma unroll
        for (int q = 0; q < 4; q++) {
            int s0 = (d + q) * 2;
            float4 wa = sgW[s0 ^ ((s0 >> 3) & 7)];
            int s1 = s0 + 1;
            float4 wb = sgW[s1 ^ ((s1 >> 3) & 7)];
            acc[0] += xs[q] * wa.x; acc[1] += xs[q] * wa.y;
            acc[2] += xs[q] * wa.z; acc[3] += xs[q] * wa.w;
            acc[4] += xs[q] * wb.x; acc[5] += xs[q] * wb.y;
            acc[6] += xs[q] * wb.z; acc[7] += xs[q] * wb.w;
        }
    }
#pragma unroll
    for (int e = 0; e < 8; e++)
#pragma unroll
        for (int o = 16; o; o >>= 1) acc[e] += __shfl_xor_sync(0xffffffffu, acc[e], o);

    if (lane == 0) {
        float lg[8];
#pragma unroll
        for (int e = 0; e < 8; e++) lg[e] = acc[e] + gb[e];
        float mx = lg[0];
#pragma unroll
        for (int e = 1; e < 8; e++) mx = fmaxf(mx, lg[e]);
        float p[8], Z = 0.f;
#pragma unroll
        for (int e = 0; e < 8; e++) { p[e] = expf(lg[e] - mx); Z += p[e]; }
        float ent = 0.f;
#pragma unroll
        for (int e = 0; e < 8; e++) {
            p[e] /= Z;
            ent -= p[e] * logf(p[e] + 1e-8f);
            sAux[wrp][e] = p[e];
        }
        sAux[wrp][8] = ent;

        int e0 = 0;
#pragma unroll
        for (int e = 1; e < 8; e++) if (lg[e] > lg[e0]) e0 = e;
        int e1 = -1;
#pragma unroll
        for (int e = 0; e < 8; e++) if (e != e0 && (e1 < 0 || lg[e] > lg[e1])) e1 = e;

        float dlt = expf(lg[e1] - lg[e0]);
        float g0 = 1.0f / (1.0f + dlt);
        float g1 = dlt / (1.0f + dlt);

        int s0 = atomicAdd(&g_cnt[e0], 1);
        g_tok[e0 * CAP + s0] = token; g_gate[e0 * CAP + s0] = g0;
        int s1 = atomicAdd(&g_cnt[e1], 1);
        g_tok[e1 * CAP + s1] = token; g_gate[e1 * CAP + s1] = g1;
        g_inv[token * 2 + 0] = e0 * CAP + s0;
        g_inv[token * 2 + 1] = e1 * CAP + s1;
    }
    __syncthreads();
    // one aux atomic set per block (8x fewer global atomics)
    if (tid < 9) {
        float v = 0.f;
#pragma unroll
        for (int w = 0; w < 8; w++) v += sAux[w][tid];
        if (tid < 8) atomicAdd(&g_imp[tid], v);
        else         atomicAdd(&g_ent, v);
    }
}

// ---------------- fp16 pipelined grouped GEMM (128x256, warp 64x64, BK=64) ----------------
// MODE 0: A = gather(g_xh) [K=1024], B=g_w1h, bias+gelu -> g_hh (half, permuted)
//         by==64 row: one block computes g_off + the 19 tail outputs
// MODE 1: A = g_hh [K=2048], B=g_w2h, gate*(bias+c) -> g_yh (half)
template <int MODE>
__global__ void __launch_bounds__(256, 1)
gemm_h(const float* __restrict__ bias, float* __restrict__ out_tail) {
    constexpr int Kdim  = (MODE == 0) ? D_DIM : H_DIM;
    constexpr int Ncols = (MODE == 0) ? H_DIM : D_DIM;
    constexpr int NS    = Kdim / BK;

    extern __shared__ char smem[];

    if (MODE == 0 && blockIdx.y >= 64) {
        // tail-output fold: one block (counters final after prelude;
        // g_off read only by gemm_h<1>/ln_k, which launch after this kernel)
        if (blockIdx.x == 0 && blockIdx.z == 0 && threadIdx.x == 0) {
            int off = 0;
            float loadv[8], impv[8];
            for (int e = 0; e < 8; e++) { g_off[e] = off; off += g_cnt[e]; }
            for (int e = 0; e < 8; e++) {
                loadv[e] = (float)g_cnt[e] / (float)N_TOK;
                impv[e]  = g_imp[e] / (float)N_TOK;
            }
            float bal = 0.f, util = 0.f;
            for (int e = 0; e < 8; e++) bal += impv[e] * loadv[e];
            bal *= (float)E_NUM;
            for (int e = 0; e < 8; e++) util -= loadv[e] * logf(loadv[e] + 1e-8f);
            out_tail[0] = bal;
            out_tail[1] = g_ent / (float)N_TOK;
            out_tail[2] = util;
            for (int e = 0; e < 8; e++) out_tail[3 + e]  = loadv[e];
            for (int e = 0; e < 8; e++) out_tail[11 + e] = impv[e];
        }
        return;
    }

    const int e = blockIdx.z;
    const int cnt = g_cnt[e];
    const int m_base = blockIdx.y * BM;
    if (m_base >= cnt) return;
    const int n_base = blockIdx.x * BN;
    // hoff: MODE 0 computes the prefix locally (g_off not yet written);
    // MODE 1 reads g_off (written during the MODE-0 kernel).
    int hoff;
    if (MODE == 0) {
        hoff = 0;
        for (int i = 0; i < e; i++) hoff += g_cnt[i];
    } else {
        hoff = g_off[e];
    }

    const int tid = threadIdx.x, wid = tid >> 5, lane = tid & 31;
    const int g = lane >> 2, tig = lane & 3;
    const int wm = (wid & 1) * 64;
    const int wn = (wid >> 1) * 64;
    const uint32_t sb = smem_u32(smem);
    float* sBias = (float*)smem;

    sBias[tid] = bias[(size_t)e * Ncols + n_base + tid];

    // ---- cp.async assignments ----
    const int cch = tid & 7;          // 16B chunk (8 halves) within 128B row
    const int r0  = tid >> 3;         // base row 0..31
    const __half* Ab = (MODE == 0) ? (const __half*)g_xh : (const __half*)g_hh;
    const __half* Wb = (MODE == 0) ? (const __half*)g_w1h : (const __half*)g_w2h;

    const __half* aSrc[4];
#pragma unroll
    for (int i = 0; i < 4; i++) {
        int am = m_base + r0 + 32 * i;
        if (am >= cnt) am = cnt - 1;
        size_t row = (MODE == 0) ? (size_t)g_tok[e * CAP + am] : (size_t)(hoff + am);
        aSrc[i] = Ab + row * Kdim + cch * 8;
    }
    const __half* bSrc = Wb + ((size_t)e * Ncols + n_base + r0) * Kdim + cch * 8;

    const uint32_t swz = (uint32_t)((cch ^ (r0 & 7)) << 4);
    const uint32_t aDst = sb + 1024 + r0 * 128 + swz;
    const uint32_t bDst = sb + 1024 + A_BYTES + r0 * 128 + swz;

    float c[4][8][4];
#pragma unroll
    for (int i = 0; i < 4; i++)
#pragma unroll
        for (int j = 0; j < 8; j++)
#pragma unroll
            for (int r = 0; r < 4; r++) c[i][j][r] = 0.f;

    auto issue = [&](int s) {
        if (s < NS) {
            const int kb = s * BK;
            const uint32_t so = (uint32_t)((s & (NSTAGE - 1)) * STAGE_BYTES);
#pragma unroll
            for (int i = 0; i < 4; i++)
                CP16(aDst + so + i * 4096, aSrc[i] + kb);
#pragma unroll
            for (int i = 0; i < 8; i++)
                CP16(bDst + so + i * 4096, bSrc + (size_t)(32 * i) * Kdim + kb);
        }
        CP_COMMIT();
    };

    issue(0); issue(1); issue(2);

    const int aRow = (wm + g) * 128;
    const int bRow = A_BYTES + (wn + g) * 128;

    for (int s = 0; s < NS; s++) {
        CP_WAIT(2);
        __syncthreads();
        issue(s + 3);

        const char* stg = smem + 1024 + (s & (NSTAGE - 1)) * STAGE_BYTES;
#pragma unroll
        for (int kx = 0; kx < 4; kx++) {
            const int off = (((2 * kx + (tig >> 1)) ^ g) << 4) + 8 * (tig & 1);
            uint2 ua0[4], ua1[4], ub[8];
#pragma unroll
            for (int i = 0; i < 4; i++) {
                ua0[i] = *(const uint2*)(stg + aRow + i * 2048 + off);
                ua1[i] = *(const uint2*)(stg + aRow + i * 2048 + 1024 + off);
            }
#pragma unroll
            for (int j = 0; j < 8; j++)
                ub[j] = *(const uint2*)(stg + bRow + j * 1024 + off);
#pragma unroll
            for (int i = 0; i < 4; i++)
#pragma unroll
                for (int j = 0; j < 8; j++)
                    mma_f16(c[i][j], ua0[i].x, ua1[i].x, ua0[i].y, ua1[i].y,
                            ub[j].x, ub[j].y);
        }
    }

    // ---- epilogue ----
#pragma unroll
    for (int i = 0; i < 4; i++) {
#pragma unroll
        for (int half = 0; half < 2; half++) {
            int mrow = m_base + wm + 16 * i + g + half * 8;
            if (mrow >= cnt) continue;
            if (MODE == 0) {
                __half* hp = g_hh + (size_t)(hoff + mrow) * H_DIM + n_base;
#pragma unroll
                for (int j = 0; j < 8; j++) {
                    int col = wn + j * 8 + tig * 2;
                    float v0 = c[i][j][half * 2 + 0] + sBias[col];
                    float v1 = c[i][j][half * 2 + 1] + sBias[col + 1];
                    int col2 = (col & ~15) + kslot(col & 15);   // permuted store
                    *reinterpret_cast<__half2*>(hp + col2) =
                        __floats2half2_rn(gelu_exact(v0), gelu_exact(v1));
                }
            } else {
                float gate = g_gate[e * CAP + mrow];
                __half* yp = g_yh + (size_t)(hoff + mrow) * D_DIM + n_base;
#pragma unroll
                for (int j = 0; j < 8; j++) {
                    int col = wn + j * 8 + tig * 2;
                    float v0 = gate * (c[i][j][half * 2 + 0] + sBias[col]);
                    float v1 = gate * (c[i][j][half * 2 + 1] + sBias[col + 1]);
                    *reinterpret_cast<__half2*>(yp + col) = __floats2half2_rn(v0, v1);
                }
            }
        }
    }
}

// ---------------- LayerNorm: 2 tokens/block, 128 threads/token, 8 floats/thread ----------------
__global__ void ln_k(const float* __restrict__ x,
                     const float* __restrict__ gamma,
                     const float* __restrict__ beta,
                     float* __restrict__ out) {
    __shared__ float ws[2][4], wq[2][4];
    int tid = threadIdx.x;
    int grp = tid >> 7, gtid = tid & 127;
    int glane = gtid & 31, gwarp = gtid >> 5;   // 4 warps per group
    int token = blockIdx.x * 2 + grp;

    // counters no longer read this launch; re-zero for next graph replay
    if (blockIdx.x == 0 && tid < 9) {
        if (tid < 8) { g_cnt[tid] = 0; g_imp[tid] = 0.0f; }
        else         g_ent = 0.0f;
    }

    int i0 = g_inv[token * 2 + 0], i1 = g_inv[token * 2 + 1];
    size_t r0 = (size_t)(g_off[i0 >> 13] + (i0 & (CAP - 1)));
    size_t r1 = (size_t)(g_off[i1 >> 13] + (i1 & (CAP - 1)));
    const __half* y0 = g_yh + r0 * D_DIM;
    const __half* y1 = g_yh + r1 * D_DIM;
    const float* xr = x + (size_t)token * D_DIM;

    const int c = gtid * 8;
    float4 xv0 = *reinterpret_cast<const float4*>(xr + c);
    float4 xv1 = *reinterpret_cast<const float4*>(xr + c + 4);
    uint4 ya = *reinterpret_cast<const uint4*>(y0 + c);   // 8 halves
    uint4 yb = *reinterpret_cast<const uint4*>(y1 + c);

    float z[8];
    {
        const __half2* ha = reinterpret_cast<const __half2*>(&ya);
        const __half2* hb = reinterpret_cast<const __half2*>(&yb);
        float xf[8] = {xv0.x, xv0.y, xv0.z, xv0.w, xv1.x, xv1.y, xv1.z, xv1.w};
#pragma unroll
        for (int k = 0; k < 4; k++) {
            float2 fa = __half22float2(ha[k]);
            float2 fb = __half22float2(hb[k]);
            z[2 * k + 0] = xf[2 * k + 0] + fa.x + fb.x;
            z[2 * k + 1] = xf[2 * k + 1] + fa.y + fb.y;
        }
    }

    float s = 0.f, sq = 0.f;
#pragma unroll
    for (int k = 0; k < 8; k++) { s += z[k]; sq += z[k] * z[k]; }
#pragma unroll
    for (int o = 16; o; o >>= 1) {
        s  += __shfl_xor_sync(0xffffffffu, s, o);
        sq += __shfl_xor_sync(0xffffffffu, sq, o);
    }
    if (glane == 0) { ws[grp][gwarp] = s; wq[grp][gwarp] = sq; }
    __syncthreads();
    float st = ws[grp][0] + ws[grp][1] + ws[grp][2] + ws[grp][3];
    float qt = wq[grp][0] + wq[grp][1] + wq[grp][2] + wq[grp][3];
    float mu  = st * (1.0f / D_DIM);
    float var = qt * (1.0f / D_DIM) - mu * mu;
    float inv = rsqrtf(var + 1e-5f);

    float* op = out + (size_t)token * D_DIM + c;
#pragma unroll
    for (int v = 0; v < 2; v++) {
        float4 gm = *reinterpret_cast<const float4*>(gamma + c + v * 4);
        float4 bt = *reinterpret_cast<const float4*>(beta + c + v * 4);
        float4 o;
        o.x = (z[v * 4 + 0] - mu) * inv * gm.x + bt.x;
        o.y = (z[v * 4 + 1] - mu) * inv * gm.y + bt.y;
        o.z = (z[v * 4 + 2] - mu) * inv * gm.z + bt.z;
        o.w = (z[v * 4 + 3] - mu) * inv * gm.w + bt.w;
        *reinterpret_cast<float4*>(op + v * 4) = o;
    }
}

// ---------------- launch ----------------
extern "C" void kernel_launch(void* const* d_in, const int* in_sizes, int n_in,
                              void* d_out, int out_size) {
    (void)in_sizes; (void)n_in; (void)out_size;
    const float* x     = (const float*)d_in[0];
    const float* gW    = (const float*)d_in[1];
    const float* gb    = (const float*)d_in[2];
    const float* W1    = (const float*)d_in[3];
    const float* b1    = (const float*)d_in[4];
    const float* W2    = (const float*)d_in[5];
    const float* b2    = (const float*)d_in[6];
    const float* gamma = (const float*)d_in[7];
    const float* beta  = (const float*)d_in[8];
    float* out = (float*)d_out;
    float* out_tail = out + (size_t)N_TOK * D_DIM;

    cudaFuncSetAttribute((const void*)gemm_h<0>,
                         cudaFuncAttributeMaxDynamicSharedMemorySize, SMEM_TOTAL);
    cudaFuncSetAttribute((const void*)gemm_h<1>,
                         cudaFuncAttributeMaxDynamicSharedMemorySize, SMEM_TOTAL);

    // router + W1 transpose + W2 transpose (all DRAM-bound, co-resident)
    prelude_k<<<1024 + 4096 + 4096, 256>>>(x, gW, gb, W1, W2);
    // pure GEMM1 (by<64) + tail outputs (by==64, one block)
    gemm_h<0><<<dim3(H_DIM / BN, 65, E_NUM), 256, SMEM_TOTAL>>>(b1, out_tail);
    gemm_h<1><<<dim3(D_DIM / BN, CAP / BM, E_NUM), 256, SMEM_TOTAL>>>(b2, nullptr);
    ln_k<<<N_TOK / 2, 256>>>(x, gamma, beta, out);       // + counter reset for next replay
}